// round 1
// baseline (speedup 1.0000x reference)
#include <cuda_runtime.h>
#include <cuda_bf16.h>

// ----------------------------------------------------------------------------
// QCNN fused kernel, fp32x2 packed (2 samples per thread-lane element).
//   prep kernel: per-tensor int8 fake-quant of weights (matches brevitas/jax)
//   main kernel: whole network fused, activations in shared memory
// ----------------------------------------------------------------------------

typedef unsigned long long u64;

__device__ float g_qw1[64];
__device__ float g_qw2[768];
__device__ float g_qw3[2560];
__device__ float g_qw4[5120];
__device__ float g_qwdT[55296];   // transposed: [j=864][o=64]
__device__ float g_qwo[64];

// ---- f32x2 helpers ---------------------------------------------------------
__device__ __forceinline__ u64 ffma2(u64 a, u64 b, u64 c) {
    u64 d;
    asm("fma.rn.f32x2 %0, %1, %2, %3;" : "=l"(d) : "l"(a), "l"(b), "l"(c));
    return d;
}
__device__ __forceinline__ u64 add2(u64 a, u64 b) {
    u64 d;
    asm("add.rn.f32x2 %0, %1, %2;" : "=l"(d) : "l"(a), "l"(b));
    return d;
}
__device__ __forceinline__ u64 pack2(float x, float y) {
    u64 d;
    asm("mov.b64 %0, {%1, %2};" : "=l"(d) : "f"(x), "f"(y));
    return d;
}
__device__ __forceinline__ float2 unpack2(u64 v) {
    float2 f;
    asm("mov.b64 {%0, %1}, %2;" : "=f"(f.x), "=f"(f.y) : "l"(v));
    return f;
}
__device__ __forceinline__ u64 dup2(float w) { return pack2(w, w); }
__device__ __forceinline__ u64 lrelu2(u64 v) {
    float2 f = unpack2(v);
    f.x = f.x > 0.0f ? f.x : 0.1f * f.x;
    f.y = f.y > 0.0f ? f.y : 0.1f * f.y;
    return pack2(f.x, f.y);
}
__device__ __forceinline__ u64 max2(u64 a, u64 b) {
    float2 fa = unpack2(a), fb = unpack2(b);
    return pack2(fmaxf(fa.x, fb.x), fmaxf(fa.y, fb.y));
}

// ---- weight quantization prep ---------------------------------------------
// q = clip(round_half_even(w / (max|w|/127)), -127, 127) * scale
__global__ void quant_prep_kernel(const float* __restrict__ w1,
                                  const float* __restrict__ w2,
                                  const float* __restrict__ w3,
                                  const float* __restrict__ w4,
                                  const float* __restrict__ wd,
                                  const float* __restrict__ wo) {
    __shared__ float red[256];
    int b = blockIdx.x, tid = threadIdx.x;
    const float* src; float* dst; int n; bool tr = false;
    if (b == 0)      { src = w1; dst = g_qw1;  n = 64; }
    else if (b == 1) { src = w2; dst = g_qw2;  n = 768; }
    else if (b == 2) { src = w3; dst = g_qw3;  n = 2560; }
    else if (b == 3) { src = w4; dst = g_qw4;  n = 5120; }
    else if (b == 4) { src = wd; dst = g_qwdT; n = 55296; tr = true; }
    else             { src = wo; dst = g_qwo;  n = 64; }

    float m = 0.0f;
    for (int i = tid; i < n; i += 256) m = fmaxf(m, fabsf(src[i]));
    red[tid] = m;
    __syncthreads();
    for (int s = 128; s > 0; s >>= 1) {
        if (tid < s) red[tid] = fmaxf(red[tid], red[tid + s]);
        __syncthreads();
    }
    float scale = red[0] / 127.0f;
    for (int i = tid; i < n; i += 256) {
        float q = rintf(src[i] / scale);           // rintf == round half-even == jnp.round
        q = fminf(fmaxf(q, -127.0f), 127.0f) * scale;
        if (tr) { int o = i / 864, j = i - o * 864; dst[j * 64 + o] = q; }
        else    { dst[i] = q; }
    }
}

// ---- fused network kernel --------------------------------------------------
// 512 threads, 8 samples (= 4 f32x2 pairs) per block, grid = 32768/8 = 4096.
//
// Dynamic smem layout (u64 units):
//   [0      ..  1032) SX   pair stride 258  (2ch x 128 + pad)
//   [1032   ..  9232) H1   pair stride 2050 (16ch x 128 + pad)
//   [0      ..  8200) H3   pair stride 2050 (32ch x 64 + pad)   -- aliases SX+H1
//   [9232   .. 13336) P1   pair stride 1026 (16ch x 64 + pad)
//   [9232   .. 12696) P2   pair stride 866  (32*27 flat + pad)  -- aliases P1
//   [13336  .. 21848) W1/W2/W3/W4 (dup-packed)
//   [21848  .. 22008) packed biases
//   [0      ..  2048) PART (dense partials, aliases dead H3)
//   [2048   ..  2304) HH   (dense hidden,   aliases dead H3)
#define SMEM_U64 22008
#define SMEM_BYTES (SMEM_U64 * 8)

__global__ void __launch_bounds__(512, 1)
qcnn_kernel(const float* __restrict__ x,
            const float* __restrict__ b1, const float* __restrict__ b2,
            const float* __restrict__ b3, const float* __restrict__ b4,
            const float* __restrict__ bd, const float* __restrict__ bo,
            float* __restrict__ out) {
    extern __shared__ u64 sm[];
    const int tid  = threadIdx.x;
    const int base = blockIdx.x * 8;

    u64* SX = sm;              // pair*258 + c*128 + l
    u64* H1 = sm + 1032;       // pair*2050 + co*128 + t
    u64* H3 = sm;              // pair*2050 + co*64 + t
    u64* P1 = sm + 9232;       // pair*1026 + co*64 + p
    u64* P2 = sm + 9232;       // pair*866 + co*27 + p
    u64* W1 = sm + 13336;      // co*4 + ci*2 + k
    u64* W2 = sm + 13400;      // co*48 + ci*3 + k
    u64* W3 = sm + 14168;      // co*80 + ci*5 + k
    u64* W4 = sm + 16728;      // co*160 + ci*5 + k
    u64* B1s = sm + 21848; u64* B2s = sm + 21864;
    u64* B3s = sm + 21880; u64* B4s = sm + 21912;
    u64* BDs = sm + 21944;
    u64* PART = sm;            // chunk*256 + oc*4 + pair
    u64* HH   = sm + 2048;     // pair*64 + oc

    // ---- stage inputs + weights --------------------------------------------
    for (int e = tid; e < 1024; e += 512) {
        int pr = e >> 8, r = e & 255;
        const float* xp = x + (base + 2 * pr) * 256 + r;
        SX[pr * 258 + r] = pack2(xp[0], xp[256]);
    }
    for (int i = tid; i < 64;   i += 512) W1[i] = dup2(g_qw1[i]);
    for (int i = tid; i < 768;  i += 512) W2[i] = dup2(g_qw2[i]);
    for (int i = tid; i < 2560; i += 512) W3[i] = dup2(g_qw3[i]);
    for (int i = tid; i < 5120; i += 512) W4[i] = dup2(g_qw4[i]);
    if (tid < 16)                        { B1s[tid] = dup2(b1[tid]); B2s[tid] = dup2(b2[tid]); }
    else if (tid >= 32 && tid < 64)      { int q = tid - 32; B3s[q] = dup2(b3[q]); B4s[q] = dup2(b4[q]); }
    else if (tid >= 64 && tid < 128)     { int q = tid - 64; BDs[q] = dup2(bd[q]); }
    __syncthreads();

    // ---- L1: conv(2->16, k=2) + lrelu, t = 0..126 --------------------------
    if (tid < 508) {
        int pr = tid & 3, t = tid >> 2;
        const u64* xs = SX + pr * 258;
        u64 a00 = xs[t], a01 = xs[t + 1], a10 = xs[128 + t], a11 = xs[128 + t + 1];
        u64* o = H1 + pr * 2050 + t;
#pragma unroll
        for (int co = 0; co < 16; co++) {
            u64 acc = B1s[co];
            acc = ffma2(a00, W1[co * 4 + 0], acc);
            acc = ffma2(a01, W1[co * 4 + 1], acc);
            acc = ffma2(a10, W1[co * 4 + 2], acc);
            acc = ffma2(a11, W1[co * 4 + 3], acc);
            o[co * 128] = lrelu2(acc);
        }
    }
    __syncthreads();

    // ---- L2: conv(16->16, k=3) + lrelu + maxpool2, p = 0..61 ---------------
    if (tid < 496) {
        int pr = tid & 3, rest = tid >> 2;
        int p = rest % 62, cog = rest / 62;          // cog: 8 couts each
        u64 acc0[8], acc1[8];
#pragma unroll
        for (int u = 0; u < 8; u++) acc0[u] = acc1[u] = B2s[cog * 8 + u];
        const u64* h = H1 + pr * 2050 + 2 * p;
        const u64* w = W2 + cog * 8 * 48;
        for (int ci = 0; ci < 16; ci++) {
            u64 a0 = h[ci * 128 + 0], a1 = h[ci * 128 + 1];
            u64 a2 = h[ci * 128 + 2], a3 = h[ci * 128 + 3];
#pragma unroll
            for (int u = 0; u < 8; u++) {
                u64 w0 = w[u * 48 + ci * 3 + 0];
                u64 w1_ = w[u * 48 + ci * 3 + 1];
                u64 w2_ = w[u * 48 + ci * 3 + 2];
                acc0[u] = ffma2(a0, w0, acc0[u]);
                acc0[u] = ffma2(a1, w1_, acc0[u]);
                acc0[u] = ffma2(a2, w2_, acc0[u]);
                acc1[u] = ffma2(a1, w0, acc1[u]);
                acc1[u] = ffma2(a2, w1_, acc1[u]);
                acc1[u] = ffma2(a3, w2_, acc1[u]);
            }
        }
        u64* o = P1 + pr * 1026 + p;
#pragma unroll
        for (int u = 0; u < 8; u++)
            o[(cog * 8 + u) * 64] = lrelu2(max2(acc0[u], acc1[u]));
    }
    __syncthreads();

    // ---- L3: conv(16->32, k=5) + lrelu, t = 0..57 --------------------------
    if (tid < 464) {
        int pr = tid & 3, rest = tid >> 2;
        int t = rest % 58, cog = rest / 58;          // cog: 16 couts each
        u64 acc[16];
#pragma unroll
        for (int u = 0; u < 16; u++) acc[u] = B3s[cog * 16 + u];
        const u64* pp = P1 + pr * 1026 + t;
        const u64* w = W3 + cog * 16 * 80;
        for (int ci = 0; ci < 16; ci++) {
            u64 a0 = pp[ci * 64 + 0], a1 = pp[ci * 64 + 1], a2 = pp[ci * 64 + 2];
            u64 a3 = pp[ci * 64 + 3], a4 = pp[ci * 64 + 4];
#pragma unroll
            for (int u = 0; u < 16; u++) {
                const u64* wi = w + u * 80 + ci * 5;
                acc[u] = ffma2(a0, wi[0], acc[u]);
                acc[u] = ffma2(a1, wi[1], acc[u]);
                acc[u] = ffma2(a2, wi[2], acc[u]);
                acc[u] = ffma2(a3, wi[3], acc[u]);
                acc[u] = ffma2(a4, wi[4], acc[u]);
            }
        }
        u64* o = H3 + pr * 2050 + t;   // overwrites dead SX/H1 region
#pragma unroll
        for (int u = 0; u < 16; u++)
            o[(cog * 16 + u) * 64] = lrelu2(acc[u]);
    }
    __syncthreads();

    // ---- L4: conv(32->32, k=5) + lrelu + maxpool2, p = 0..26 ---------------
    if (tid < 432) {
        int pr = tid & 3, rest = tid >> 2;
        int p = rest % 27, cog = rest / 27;          // cog: 8 couts each (4 groups)
        u64 acc0[8], acc1[8];
#pragma unroll
        for (int u = 0; u < 8; u++) acc0[u] = acc1[u] = B4s[cog * 8 + u];
        const u64* h = H3 + pr * 2050 + 2 * p;
        const u64* w = W4 + cog * 8 * 160;
        for (int ci = 0; ci < 32; ci++) {
            u64 a0 = h[ci * 64 + 0], a1 = h[ci * 64 + 1], a2 = h[ci * 64 + 2];
            u64 a3 = h[ci * 64 + 3], a4 = h[ci * 64 + 4], a5 = h[ci * 64 + 5];
#pragma unroll
            for (int u = 0; u < 8; u++) {
                const u64* wi = w + u * 160 + ci * 5;
                u64 w0 = wi[0], w1_ = wi[1], w2_ = wi[2], w3_ = wi[3], w4_ = wi[4];
                acc0[u] = ffma2(a0, w0, acc0[u]);
                acc0[u] = ffma2(a1, w1_, acc0[u]);
                acc0[u] = ffma2(a2, w2_, acc0[u]);
                acc0[u] = ffma2(a3, w3_, acc0[u]);
                acc0[u] = ffma2(a4, w4_, acc0[u]);
                acc1[u] = ffma2(a1, w0, acc1[u]);
                acc1[u] = ffma2(a2, w1_, acc1[u]);
                acc1[u] = ffma2(a3, w2_, acc1[u]);
                acc1[u] = ffma2(a4, w3_, acc1[u]);
                acc1[u] = ffma2(a5, w4_, acc1[u]);
            }
        }
        u64* o = P2 + pr * 866 + p;    // flat layout co*27+p (aliases dead P1)
#pragma unroll
        for (int u = 0; u < 8; u++)
            o[(cog * 8 + u) * 27] = lrelu2(max2(acc0[u], acc1[u]));
    }
    __syncthreads();

    // ---- dense 864 -> 64 (partials over 8 j-chunks of 108) -----------------
    {
        int oc = tid & 63, chunk = tid >> 6;
        u64 acc[4] = {0ull, 0ull, 0ull, 0ull};
        int j0 = chunk * 108;
        const float* wt = g_qwdT + j0 * 64 + oc;     // coalesced across oc
#pragma unroll 4
        for (int jj = 0; jj < 108; jj++) {
            u64 wp = dup2(__ldg(wt + jj * 64));
#pragma unroll
            for (int q = 0; q < 4; q++)
                acc[q] = ffma2(P2[q * 866 + j0 + jj], wp, acc[q]);
        }
#pragma unroll
        for (int q = 0; q < 4; q++)
            PART[chunk * 256 + oc * 4 + q] = acc[q];   // PART aliases dead H3
    }
    __syncthreads();

    // ---- reduce partials + bias + lrelu ------------------------------------
    if (tid < 256) {
        int oc = tid & 63, q = tid >> 6;
        u64 s = PART[oc * 4 + q];
#pragma unroll
        for (int c = 1; c < 8; c++) s = add2(s, PART[c * 256 + oc * 4 + q]);
        s = add2(s, BDs[oc]);
        HH[q * 64 + oc] = lrelu2(s);
    }
    __syncthreads();

    // ---- output 64 -> 1 (warp per pair, shuffle reduction) -----------------
    if (tid < 128) {
        int q = tid >> 5, lane = tid & 31;
        float2 h0 = unpack2(HH[q * 64 + lane]);
        float2 h1v = unpack2(HH[q * 64 + 32 + lane]);
        float wl = g_qwo[lane], wh = g_qwo[lane + 32];
        float ax = h0.x * wl + h1v.x * wh;
        float ay = h0.y * wl + h1v.y * wh;
#pragma unroll
        for (int o = 16; o > 0; o >>= 1) {
            ax += __shfl_xor_sync(0xffffffffu, ax, o);
            ay += __shfl_xor_sync(0xffffffffu, ay, o);
        }
        if (lane == 0) {
            float bov = bo[0];
            reinterpret_cast<float2*>(out)[blockIdx.x * 4 + q] =
                make_float2(ax + bov, ay + bov);
        }
    }
}

// ---- launcher --------------------------------------------------------------
extern "C" void kernel_launch(void* const* d_in, const int* in_sizes, int n_in,
                              void* d_out, int out_size) {
    const float* x  = (const float*)d_in[0];
    const float* w1 = (const float*)d_in[1];
    const float* b1 = (const float*)d_in[2];
    const float* w2 = (const float*)d_in[3];
    const float* b2 = (const float*)d_in[4];
    const float* w3 = (const float*)d_in[5];
    const float* b3 = (const float*)d_in[6];
    const float* w4 = (const float*)d_in[7];
    const float* b4 = (const float*)d_in[8];
    const float* wd = (const float*)d_in[9];
    const float* bd = (const float*)d_in[10];
    const float* wo = (const float*)d_in[11];
    const float* bo = (const float*)d_in[12];

    cudaFuncSetAttribute(qcnn_kernel,
                         cudaFuncAttributeMaxDynamicSharedMemorySize, SMEM_BYTES);

    quant_prep_kernel<<<6, 256>>>(w1, w2, w3, w4, wd, wo);

    int blocks = 32768 / 8;   // 8 samples per block
    qcnn_kernel<<<blocks, 512, SMEM_BYTES>>>(x, b1, b2, b3, b4, bd, bo,
                                             (float*)d_out);
}

// round 2
// speedup vs baseline: 1.8214x; 1.8214x over previous
#include <cuda_runtime.h>
#include <cuda_bf16.h>

// ----------------------------------------------------------------------------
// QCNN fused kernel, fp32x2 packed (2 samples per lane element), round 2:
// vectorized LDS.128 smem traffic + register blocking (was LDS-bound at 82% L1).
// ----------------------------------------------------------------------------

typedef unsigned long long u64;

__device__ float g_qw1[64];
__device__ float g_qw2[768];
__device__ float g_qw3[2560];
__device__ float g_qw4[5120];
__device__ float g_qwdT[55296];   // transposed: [j=864][o=64]
__device__ float g_qwo[64];

// ---- f32x2 helpers ---------------------------------------------------------
__device__ __forceinline__ u64 ffma2(u64 a, u64 b, u64 c) {
    u64 d;
    asm("fma.rn.f32x2 %0, %1, %2, %3;" : "=l"(d) : "l"(a), "l"(b), "l"(c));
    return d;
}
__device__ __forceinline__ u64 add2(u64 a, u64 b) {
    u64 d;
    asm("add.rn.f32x2 %0, %1, %2;" : "=l"(d) : "l"(a), "l"(b));
    return d;
}
__device__ __forceinline__ u64 pack2(float x, float y) {
    u64 d;
    asm("mov.b64 %0, {%1, %2};" : "=l"(d) : "f"(x), "f"(y));
    return d;
}
__device__ __forceinline__ float2 unpack2(u64 v) {
    float2 f;
    asm("mov.b64 {%0, %1}, %2;" : "=f"(f.x), "=f"(f.y) : "l"(v));
    return f;
}
__device__ __forceinline__ u64 dup2(float w) { return pack2(w, w); }
__device__ __forceinline__ u64 lrelu2(u64 v) {
    float2 f = unpack2(v);
    f.x = f.x > 0.0f ? f.x : 0.1f * f.x;
    f.y = f.y > 0.0f ? f.y : 0.1f * f.y;
    return pack2(f.x, f.y);
}
__device__ __forceinline__ u64 max2(u64 a, u64 b) {
    float2 fa = unpack2(a), fb = unpack2(b);
    return pack2(fmaxf(fa.x, fb.x), fmaxf(fa.y, fb.y));
}
__device__ __forceinline__ ulonglong2 lds2(const u64* p) {
    return *reinterpret_cast<const ulonglong2*>(p);
}

// ---- weight quantization prep ---------------------------------------------
__global__ void quant_prep_kernel(const float* __restrict__ w1,
                                  const float* __restrict__ w2,
                                  const float* __restrict__ w3,
                                  const float* __restrict__ w4,
                                  const float* __restrict__ wd,
                                  const float* __restrict__ wo) {
    __shared__ float red[256];
    int b = blockIdx.x, tid = threadIdx.x;
    const float* src; float* dst; int n; bool tr = false;
    if (b == 0)      { src = w1; dst = g_qw1;  n = 64; }
    else if (b == 1) { src = w2; dst = g_qw2;  n = 768; }
    else if (b == 2) { src = w3; dst = g_qw3;  n = 2560; }
    else if (b == 3) { src = w4; dst = g_qw4;  n = 5120; }
    else if (b == 4) { src = wd; dst = g_qwdT; n = 55296; tr = true; }
    else             { src = wo; dst = g_qwo;  n = 64; }

    float m = 0.0f;
    for (int i = tid; i < n; i += 256) m = fmaxf(m, fabsf(src[i]));
    red[tid] = m;
    __syncthreads();
    for (int s = 128; s > 0; s >>= 1) {
        if (tid < s) red[tid] = fmaxf(red[tid], red[tid + s]);
        __syncthreads();
    }
    float scale = red[0] / 127.0f;
    for (int i = tid; i < n; i += 256) {
        float q = rintf(src[i] / scale);           // round half-even == jnp.round
        q = fminf(fmaxf(q, -127.0f), 127.0f) * scale;
        if (tr) { int o = i / 864, j = i - o * 864; dst[j * 64 + o] = q; }
        else    { dst[i] = q; }
    }
}

// ---- fused network kernel --------------------------------------------------
// 512 threads, 8 samples (= 4 f32x2 pairs) per block, grid = 4096.
//
// smem (u64 units):
//   SX   0      (4 x 258)                     pr*258 + c*128 + t
//   H1   1032   (4 x 2050)                    pr*2050 + co*128 + t
//   H3   0      (4 x 2050, aliases SX+H1)     pr*2050 + co*64 + t
//   P1   9232   (4 x 1026)                    pr*1026 + co*64 + p
//   P2   9232   (4 x 866, aliases P1)         q*866 + co*27 + p
//   W1   13336  (64)        co*4 + ci*2 + k
//   W2   13400  (1024)      (co*16+ci)*4 + k   (k padded 3->4)
//   W3   14424  (3072)      (co*16+ci)*6 + k   (k padded 5->6)
//   W4   17496  (6144)      (co*32+ci)*6 + k   (k padded 5->6)
//   biases 23640..23800
//   PART 0 (2048), HH 2048 (256)  (alias dead H3 during dense)
#define SMEM_U64 23800
#define SMEM_BYTES (SMEM_U64 * 8)

__global__ void __launch_bounds__(512, 1)
qcnn_kernel(const float* __restrict__ x,
            const float* __restrict__ b1, const float* __restrict__ b2,
            const float* __restrict__ b3, const float* __restrict__ b4,
            const float* __restrict__ bd, const float* __restrict__ bo,
            float* __restrict__ out) {
    extern __shared__ u64 sm[];
    const int tid  = threadIdx.x;
    const int base = blockIdx.x * 8;

    u64* SX = sm;
    u64* H1 = sm + 1032;
    u64* H3 = sm;
    u64* P1 = sm + 9232;
    u64* P2 = sm + 9232;
    u64* W1 = sm + 13336;
    u64* W2 = sm + 13400;
    u64* W3 = sm + 14424;
    u64* W4 = sm + 17496;
    u64* B1s = sm + 23640; u64* B2s = sm + 23656;
    u64* B3s = sm + 23672; u64* B4s = sm + 23704;
    u64* BDs = sm + 23736;
    u64* PART = sm;
    u64* HH   = sm + 2048;

    // ---- stage inputs + weights --------------------------------------------
    for (int e = tid; e < 1024; e += 512) {
        int pr = e >> 8, r = e & 255;
        const float* xp = x + (base + 2 * pr) * 256 + r;
        SX[pr * 258 + r] = pack2(xp[0], xp[256]);
    }
    for (int i = tid; i < 64; i += 512) W1[i] = dup2(g_qw1[i]);
    for (int i = tid; i < 1024; i += 512) {
        int co = i >> 6, ci = (i >> 2) & 15, k = i & 3;
        W2[i] = dup2(k < 3 ? g_qw2[co * 48 + ci * 3 + k] : 0.0f);
    }
    for (int i = tid; i < 3072; i += 512) {
        int co = i / 96, r = i - co * 96, ci = r / 6, k = r - ci * 6;
        W3[i] = dup2(k < 5 ? g_qw3[(co * 16 + ci) * 5 + k] : 0.0f);
    }
    for (int i = tid; i < 6144; i += 512) {
        int co = i / 192, r = i - co * 192, ci = r / 6, k = r - ci * 6;
        W4[i] = dup2(k < 5 ? g_qw4[(co * 32 + ci) * 5 + k] : 0.0f);
    }
    if (tid < 16)                    { B1s[tid] = dup2(b1[tid]); B2s[tid] = dup2(b2[tid]); }
    else if (tid >= 32 && tid < 64)  { int q = tid - 32; B3s[q] = dup2(b3[q]); B4s[q] = dup2(b4[q]); }
    else if (tid >= 64 && tid < 128) { int q = tid - 64; BDs[q] = dup2(bd[q]); }
    __syncthreads();

    // ---- L1: conv(2->16, k=2) + lrelu, t = 0..126 --------------------------
    if (tid < 508) {
        int pr = tid & 3, t = tid >> 2;
        const u64* xs = SX + pr * 258;
        u64 a00 = xs[t], a01 = xs[t + 1], a10 = xs[128 + t], a11 = xs[128 + t + 1];
        u64* o = H1 + pr * 2050 + t;
#pragma unroll
        for (int co = 0; co < 16; co++) {
            ulonglong2 w01 = lds2(W1 + co * 4);
            ulonglong2 w23 = lds2(W1 + co * 4 + 2);
            u64 acc = B1s[co];
            acc = ffma2(a00, w01.x, acc);
            acc = ffma2(a01, w01.y, acc);
            acc = ffma2(a10, w23.x, acc);
            acc = ffma2(a11, w23.y, acc);
            o[co * 128] = lrelu2(acc);
        }
    }
    __syncthreads();

    // ---- L2: conv(16->16, k=3) + lrelu + pool; pooled p = pq, pq+31 --------
    if (tid < 496) {
        int pq = tid % 31, r = tid / 31;
        int pr = r & 3, cog = r >> 2;              // cog: 4 couts each
        const u64* hb = H1 + pr * 2050 + 2 * pq;
        u64 acc[16];
#pragma unroll
        for (int u = 0; u < 4; u++) {
            u64 b = B2s[cog * 4 + u];
            acc[u*4+0] = acc[u*4+1] = acc[u*4+2] = acc[u*4+3] = b;
        }
        for (int ci = 0; ci < 16; ci++) {
            const u64* h = hb + ci * 128;
            ulonglong2 aA0 = lds2(h),      aA1 = lds2(h + 2);   // t: 2pq..2pq+3
            ulonglong2 aB0 = lds2(h + 62), aB1 = lds2(h + 64);  // t: 2pq+62..+65
#pragma unroll
            for (int u = 0; u < 4; u++) {
                const u64* wp = W2 + ((cog * 4 + u) * 16 + ci) * 4;
                ulonglong2 w01 = lds2(wp), w23 = lds2(wp + 2);  // w23.x = k2
                u64* a = acc + u * 4;
                a[0]=ffma2(aA0.x,w01.x,a[0]); a[0]=ffma2(aA0.y,w01.y,a[0]); a[0]=ffma2(aA1.x,w23.x,a[0]);
                a[1]=ffma2(aA0.y,w01.x,a[1]); a[1]=ffma2(aA1.x,w01.y,a[1]); a[1]=ffma2(aA1.y,w23.x,a[1]);
                a[2]=ffma2(aB0.x,w01.x,a[2]); a[2]=ffma2(aB0.y,w01.y,a[2]); a[2]=ffma2(aB1.x,w23.x,a[2]);
                a[3]=ffma2(aB0.y,w01.x,a[3]); a[3]=ffma2(aB1.x,w01.y,a[3]); a[3]=ffma2(aB1.y,w23.x,a[3]);
            }
        }
        u64* o = P1 + pr * 1026 + pq;
#pragma unroll
        for (int u = 0; u < 4; u++) {
            int co = cog * 4 + u;
            o[co * 64]      = lrelu2(max2(acc[u*4+0], acc[u*4+1]));
            o[co * 64 + 31] = lrelu2(max2(acc[u*4+2], acc[u*4+3]));
        }
    }
    __syncthreads();

    // ---- L3: conv(16->32, k=5) + lrelu, t = 2tg, 2tg+1 ---------------------
    if (tid < 464) {
        int tg = tid % 29, r = tid / 29;
        int pr = r & 3, cog = r >> 2;              // cog: 8 couts each
        const u64* pb = P1 + pr * 1026 + 2 * tg;
        u64 acc[16];
#pragma unroll
        for (int u = 0; u < 8; u++) { u64 b = B3s[cog * 8 + u]; acc[u*2] = acc[u*2+1] = b; }
        for (int ci = 0; ci < 16; ci++) {
            const u64* p = pb + ci * 64;
            ulonglong2 a01 = lds2(p), a23 = lds2(p + 2), a45 = lds2(p + 4);
#pragma unroll
            for (int u = 0; u < 8; u++) {
                const u64* wp = W3 + ((cog * 8 + u) * 16 + ci) * 6;
                ulonglong2 w01 = lds2(wp), w23 = lds2(wp + 2), w45 = lds2(wp + 4);
                u64 s0 = acc[u*2], s1 = acc[u*2+1];
                s0=ffma2(a01.x,w01.x,s0); s0=ffma2(a01.y,w01.y,s0); s0=ffma2(a23.x,w23.x,s0);
                s0=ffma2(a23.y,w23.y,s0); s0=ffma2(a45.x,w45.x,s0);
                s1=ffma2(a01.y,w01.x,s1); s1=ffma2(a23.x,w01.y,s1); s1=ffma2(a23.y,w23.x,s1);
                s1=ffma2(a45.x,w23.y,s1); s1=ffma2(a45.y,w45.x,s1);
                acc[u*2] = s0; acc[u*2+1] = s1;
            }
        }
#pragma unroll
        for (int u = 0; u < 8; u++) {
            int co = cog * 8 + u;
            ulonglong2 v;
            v.x = lrelu2(acc[u*2]); v.y = lrelu2(acc[u*2+1]);
            *reinterpret_cast<ulonglong2*>(H3 + pr * 2050 + co * 64 + 2 * tg) = v;
        }
    }
    __syncthreads();

    // ---- L4: conv(32->32, k=5) + lrelu + pool; pooled p = pq, pq+14 --------
    if (tid < 448) {
        int pq = tid % 14, r = tid / 14;
        int pr = r & 3, cog = r >> 2;              // cog: 4 couts each (8 groups)
        const u64* hb = H3 + pr * 2050 + 2 * pq;
        u64 acc[16];
#pragma unroll
        for (int u = 0; u < 4; u++) {
            u64 b = B4s[cog * 4 + u];
            acc[u*4+0] = acc[u*4+1] = acc[u*4+2] = acc[u*4+3] = b;
        }
        for (int ci = 0; ci < 32; ci++) {
            const u64* h = hb + ci * 64;
            ulonglong2 a01 = lds2(h),      a23 = lds2(h + 2),  a45 = lds2(h + 4);
            ulonglong2 c01 = lds2(h + 28), c23 = lds2(h + 30), c45 = lds2(h + 32);
#pragma unroll
            for (int u = 0; u < 4; u++) {
                const u64* wp = W4 + ((cog * 4 + u) * 32 + ci) * 6;
                ulonglong2 w01 = lds2(wp), w23 = lds2(wp + 2), w45 = lds2(wp + 4);
                u64* a = acc + u * 4;
                a[0]=ffma2(a01.x,w01.x,a[0]); a[0]=ffma2(a01.y,w01.y,a[0]); a[0]=ffma2(a23.x,w23.x,a[0]);
                a[0]=ffma2(a23.y,w23.y,a[0]); a[0]=ffma2(a45.x,w45.x,a[0]);
                a[1]=ffma2(a01.y,w01.x,a[1]); a[1]=ffma2(a23.x,w01.y,a[1]); a[1]=ffma2(a23.y,w23.x,a[1]);
                a[1]=ffma2(a45.x,w23.y,a[1]); a[1]=ffma2(a45.y,w45.x,a[1]);
                a[2]=ffma2(c01.x,w01.x,a[2]); a[2]=ffma2(c01.y,w01.y,a[2]); a[2]=ffma2(c23.x,w23.x,a[2]);
                a[2]=ffma2(c23.y,w23.y,a[2]); a[2]=ffma2(c45.x,w45.x,a[2]);
                a[3]=ffma2(c01.y,w01.x,a[3]); a[3]=ffma2(c23.x,w01.y,a[3]); a[3]=ffma2(c23.y,w23.x,a[3]);
                a[3]=ffma2(c45.x,w23.y,a[3]); a[3]=ffma2(c45.y,w45.x,a[3]);
            }
        }
#pragma unroll
        for (int u = 0; u < 4; u++) {
            int co = cog * 4 + u;
            u64* o = P2 + pr * 866 + co * 27;
            o[pq] = lrelu2(max2(acc[u*4+0], acc[u*4+1]));
            if (pq + 14 < 27)
                o[pq + 14] = lrelu2(max2(acc[u*4+2], acc[u*4+3]));
        }
    }
    __syncthreads();

    // ---- dense 864 -> 64: 256 threads, 2 oc x 4 pairs each -----------------
    if (tid < 256) {
        int oc = tid & 31, chunk = tid >> 5;
        int j0 = chunk * 108;
        u64 acc[8] = {0,0,0,0,0,0,0,0};
#pragma unroll 3
        for (int g = 0; g < 54; g++) {
            int j = j0 + 2 * g;
            const float* wr = g_qwdT + j * 64 + oc;
            u64 w0a = dup2(__ldg(wr));      u64 w0b = dup2(__ldg(wr + 32));
            u64 w1a = dup2(__ldg(wr + 64)); u64 w1b = dup2(__ldg(wr + 96));
#pragma unroll
            for (int q = 0; q < 4; q++) {
                ulonglong2 a = lds2(P2 + q * 866 + j);
                acc[q]     = ffma2(a.x, w0a, acc[q]);
                acc[q]     = ffma2(a.y, w1a, acc[q]);
                acc[q + 4] = ffma2(a.x, w0b, acc[q + 4]);
                acc[q + 4] = ffma2(a.y, w1b, acc[q + 4]);
            }
        }
#pragma unroll
        for (int q = 0; q < 4; q++) {
            PART[chunk * 256 + oc * 4 + q]        = acc[q];
            PART[chunk * 256 + (oc + 32) * 4 + q] = acc[q + 4];
        }
    }
    __syncthreads();

    // ---- reduce partials + bias + lrelu ------------------------------------
    if (tid < 256) {
        int oc = tid & 63, q = tid >> 6;
        u64 s = PART[oc * 4 + q];
#pragma unroll
        for (int c = 1; c < 8; c++) s = add2(s, PART[c * 256 + oc * 4 + q]);
        s = add2(s, BDs[oc]);
        HH[q * 64 + oc] = lrelu2(s);
    }
    __syncthreads();

    // ---- output 64 -> 1 ----------------------------------------------------
    if (tid < 128) {
        int q = tid >> 5, lane = tid & 31;
        float2 h0  = unpack2(HH[q * 64 + lane]);
        float2 h1v = unpack2(HH[q * 64 + 32 + lane]);
        float wl = g_qwo[lane], wh = g_qwo[lane + 32];
        float ax = h0.x * wl + h1v.x * wh;
        float ay = h0.y * wl + h1v.y * wh;
#pragma unroll
        for (int o = 16; o > 0; o >>= 1) {
            ax += __shfl_xor_sync(0xffffffffu, ax, o);
            ay += __shfl_xor_sync(0xffffffffu, ay, o);
        }
        if (lane == 0) {
            float bov = bo[0];
            reinterpret_cast<float2*>(out)[blockIdx.x * 4 + q] =
                make_float2(ax + bov, ay + bov);
        }
    }
}

// ---- launcher --------------------------------------------------------------
extern "C" void kernel_launch(void* const* d_in, const int* in_sizes, int n_in,
                              void* d_out, int out_size) {
    const float* x  = (const float*)d_in[0];
    const float* w1 = (const float*)d_in[1];
    const float* b1 = (const float*)d_in[2];
    const float* w2 = (const float*)d_in[3];
    const float* b2 = (const float*)d_in[4];
    const float* w3 = (const float*)d_in[5];
    const float* b3 = (const float*)d_in[6];
    const float* w4 = (const float*)d_in[7];
    const float* b4 = (const float*)d_in[8];
    const float* wd = (const float*)d_in[9];
    const float* bd = (const float*)d_in[10];
    const float* wo = (const float*)d_in[11];
    const float* bo = (const float*)d_in[12];

    cudaFuncSetAttribute(qcnn_kernel,
                         cudaFuncAttributeMaxDynamicSharedMemorySize, SMEM_BYTES);

    quant_prep_kernel<<<6, 256>>>(w1, w2, w3, w4, wd, wo);

    qcnn_kernel<<<4096, 512, SMEM_BYTES>>>(x, b1, b2, b3, b4, bd, bo,
                                           (float*)d_out);
}

// round 3
// speedup vs baseline: 1.8708x; 1.0271x over previous
#include <cuda_runtime.h>
#include <cuda_bf16.h>

// ----------------------------------------------------------------------------
// QCNN fused, f32x2 sample-pairs. Round 3: lanes=cout in L3/L4 (broadcast act
// loads), scalar weight tables, 4 samples/block -> 2 CTAs/SM (occ 25->50%).
// ----------------------------------------------------------------------------

typedef unsigned long long u64;

__device__ float g_qw1[64];
__device__ float g_qw2[768];
__device__ float g_qw3[2560];
__device__ float g_qw4[5120];
__device__ float g_qwdP[55296];   // permuted: [idx=pq*32+co][oc=64]
__device__ float g_qwo[64];

// ---- f32x2 helpers ---------------------------------------------------------
__device__ __forceinline__ u64 ffma2(u64 a, u64 b, u64 c) {
    u64 d;
    asm("fma.rn.f32x2 %0, %1, %2, %3;" : "=l"(d) : "l"(a), "l"(b), "l"(c));
    return d;
}
__device__ __forceinline__ u64 add2(u64 a, u64 b) {
    u64 d;
    asm("add.rn.f32x2 %0, %1, %2;" : "=l"(d) : "l"(a), "l"(b));
    return d;
}
__device__ __forceinline__ u64 pack2(float x, float y) {
    u64 d;
    asm("mov.b64 %0, {%1, %2};" : "=l"(d) : "f"(x), "f"(y));
    return d;
}
__device__ __forceinline__ float2 unpack2(u64 v) {
    float2 f;
    asm("mov.b64 {%0, %1}, %2;" : "=f"(f.x), "=f"(f.y) : "l"(v));
    return f;
}
__device__ __forceinline__ u64 dup2(float w) { return pack2(w, w); }
__device__ __forceinline__ u64 lrelu2(u64 v) {
    float2 f = unpack2(v);
    f.x = f.x > 0.0f ? f.x : 0.1f * f.x;
    f.y = f.y > 0.0f ? f.y : 0.1f * f.y;
    return pack2(f.x, f.y);
}
__device__ __forceinline__ u64 max2(u64 a, u64 b) {
    float2 fa = unpack2(a), fb = unpack2(b);
    return pack2(fmaxf(fa.x, fb.x), fmaxf(fa.y, fb.y));
}
__device__ __forceinline__ ulonglong2 lds2(const u64* p) {
    return *reinterpret_cast<const ulonglong2*>(p);
}

// ---- weight quantization prep ---------------------------------------------
__global__ void quant_prep_kernel(const float* __restrict__ w1,
                                  const float* __restrict__ w2,
                                  const float* __restrict__ w3,
                                  const float* __restrict__ w4,
                                  const float* __restrict__ wd,
                                  const float* __restrict__ wo) {
    __shared__ float red[256];
    int b = blockIdx.x, tid = threadIdx.x;
    const float* src; float* dst; int n; bool tr = false;
    if (b == 0)      { src = w1; dst = g_qw1;  n = 64; }
    else if (b == 1) { src = w2; dst = g_qw2;  n = 768; }
    else if (b == 2) { src = w3; dst = g_qw3;  n = 2560; }
    else if (b == 3) { src = w4; dst = g_qw4;  n = 5120; }
    else if (b == 4) { src = wd; dst = g_qwdP; n = 55296; tr = true; }
    else             { src = wo; dst = g_qwo;  n = 64; }

    float m = 0.0f;
    for (int i = tid; i < n; i += 256) m = fmaxf(m, fabsf(src[i]));
    red[tid] = m;
    __syncthreads();
    for (int s = 128; s > 0; s >>= 1) {
        if (tid < s) red[tid] = fmaxf(red[tid], red[tid + s]);
        __syncthreads();
    }
    float scale = red[0] / 127.0f;
    for (int i = tid; i < n; i += 256) {
        float q = rintf(src[i] / scale);           // round half-even == jnp.round
        q = fminf(fmaxf(q, -127.0f), 127.0f) * scale;
        if (tr) {
            int o = i / 864, j = i - o * 864;      // j = co*27 + pq
            int co = j / 27, pq = j - co * 27;
            dst[(pq * 32 + co) * 64 + o] = q;      // idx = pq*32+co
        } else dst[i] = q;
    }
}

// ---- fused network kernel --------------------------------------------------
// 512 threads, 4 samples (2 pairs) / block, 8192 blocks, 2 CTAs/SM.
//
// smem (u64):
//   SX   0     (2x258)    pr*258 + c*128 + t
//   H1   516   (2x2050)   pr*2050 + ci*128 + t
//   H3   0     (2x2050)   pr*2050 + t*32 + co      (alias SX+H1)
//   P1   4616  (2x1026)   pr*1026 + ci*64 + p
//   P2   4616  (2x866)    pr*866 + pq*32 + co      (alias P1)
//   W1   6668  (64, dup)
//   W2   6732  (1024, dup, k pad 4)
//   W3f  7756  (2560 floats = 1280 u64)  [ci*5+k]*32 + co
//   W4f  9036  (5120 floats = 2560 u64)  [ci*5+k]*32 + co
//   B*   11596..11756
//   PART 0 (1024), HH 1024 (128)   (alias dead H3)
#define SMEM_U64 11756
#define SMEM_BYTES (SMEM_U64 * 8)

__global__ void __launch_bounds__(512, 2)
qcnn_kernel(const float* __restrict__ x,
            const float* __restrict__ b1, const float* __restrict__ b2,
            const float* __restrict__ b3, const float* __restrict__ b4,
            const float* __restrict__ bd, const float* __restrict__ bo,
            float* __restrict__ out) {
    extern __shared__ u64 sm[];
    const int tid  = threadIdx.x;
    const int wrp  = tid >> 5;
    const int lane = tid & 31;
    const int base = blockIdx.x * 4;

    u64* SX = sm;
    u64* H1 = sm + 516;
    u64* H3 = sm;
    u64* P1 = sm + 4616;
    u64* P2 = sm + 4616;
    u64* W1 = sm + 6668;
    u64* W2 = sm + 6732;
    float* W3f = (float*)(sm + 7756);
    float* W4f = (float*)(sm + 9036);
    u64* B1s = sm + 11596; u64* B2s = sm + 11612;
    u64* B3s = sm + 11628; u64* B4s = sm + 11660;
    u64* BDs = sm + 11692;
    u64* PART = sm;
    u64* HH   = sm + 1024;

    // ---- stage inputs + weights --------------------------------------------
    {
        int pr = tid >> 8, r = tid & 255;
        const float* xp = x + (base + 2 * pr) * 256 + r;
        SX[pr * 258 + r] = pack2(xp[0], xp[256]);
    }
    for (int i = tid; i < 64; i += 512) W1[i] = dup2(g_qw1[i]);
    for (int i = tid; i < 1024; i += 512) {
        int co = i >> 6, ci = (i >> 2) & 15, k = i & 3;
        W2[i] = dup2(k < 3 ? g_qw2[co * 48 + ci * 3 + k] : 0.0f);
    }
    for (int i = tid; i < 2560; i += 512) {
        int co = i & 31, r = i >> 5, ci = r / 5, k = r - ci * 5;
        W3f[i] = g_qw3[(co * 16 + ci) * 5 + k];
    }
    for (int i = tid; i < 5120; i += 512) {
        int co = i & 31, r = i >> 5, ci = r / 5, k = r - ci * 5;
        W4f[i] = g_qw4[(co * 32 + ci) * 5 + k];
    }
    if (tid < 16)                    { B1s[tid] = dup2(b1[tid]); B2s[tid] = dup2(b2[tid]); }
    else if (tid >= 32 && tid < 64)  { int q = tid - 32; B3s[q] = dup2(b3[q]); B4s[q] = dup2(b4[q]); }
    else if (tid >= 64 && tid < 128) { int q = tid - 64; BDs[q] = dup2(bd[q]); }
    __syncthreads();

    // ---- L1: conv(2->16, k=2) + lrelu, t = 0..126 --------------------------
    if (tid < 508) {
        int cg = tid & 1, pr = (tid >> 1) & 1, t = tid >> 2;
        const u64* xs = SX + pr * 258;
        u64 a00 = xs[t], a01 = xs[t + 1], a10 = xs[128 + t], a11 = xs[128 + t + 1];
        u64* o = H1 + pr * 2050 + t;
#pragma unroll
        for (int u = 0; u < 8; u++) {
            int co = cg * 8 + u;
            ulonglong2 w01 = lds2(W1 + co * 4);
            ulonglong2 w23 = lds2(W1 + co * 4 + 2);
            u64 acc = B1s[co];
            acc = ffma2(a00, w01.x, acc);
            acc = ffma2(a01, w01.y, acc);
            acc = ffma2(a10, w23.x, acc);
            acc = ffma2(a11, w23.y, acc);
            o[co * 128] = lrelu2(acc);
        }
    }
    __syncthreads();

    // ---- L2: conv(16->16, k=3) + lrelu + pool; pooled p = pq, pq+31 --------
    if (tid < 496) {
        int pq = tid % 31, r = tid / 31;
        int pr = r & 1, cog = r >> 1;              // 8 groups x 2 couts
        const u64* hb = H1 + pr * 2050 + 2 * pq;
        u64 acc[8];
#pragma unroll
        for (int u = 0; u < 2; u++) {
            u64 b = B2s[cog * 2 + u];
            acc[u*4+0] = acc[u*4+1] = acc[u*4+2] = acc[u*4+3] = b;
        }
        for (int ci = 0; ci < 16; ci++) {
            const u64* h = hb + ci * 128;
            ulonglong2 aA0 = lds2(h),      aA1 = lds2(h + 2);
            ulonglong2 aB0 = lds2(h + 62), aB1 = lds2(h + 64);
#pragma unroll
            for (int u = 0; u < 2; u++) {
                const u64* wp = W2 + ((cog * 2 + u) * 16 + ci) * 4;
                ulonglong2 w01 = lds2(wp), w23 = lds2(wp + 2);
                u64* a = acc + u * 4;
                a[0]=ffma2(aA0.x,w01.x,a[0]); a[0]=ffma2(aA0.y,w01.y,a[0]); a[0]=ffma2(aA1.x,w23.x,a[0]);
                a[1]=ffma2(aA0.y,w01.x,a[1]); a[1]=ffma2(aA1.x,w01.y,a[1]); a[1]=ffma2(aA1.y,w23.x,a[1]);
                a[2]=ffma2(aB0.x,w01.x,a[2]); a[2]=ffma2(aB0.y,w01.y,a[2]); a[2]=ffma2(aB1.x,w23.x,a[2]);
                a[3]=ffma2(aB0.y,w01.x,a[3]); a[3]=ffma2(aB1.x,w01.y,a[3]); a[3]=ffma2(aB1.y,w23.x,a[3]);
            }
        }
        u64* o = P1 + pr * 1026 + pq;
#pragma unroll
        for (int u = 0; u < 2; u++) {
            int co = cog * 2 + u;
            o[co * 64]      = lrelu2(max2(acc[u*4+0], acc[u*4+1]));
            o[co * 64 + 31] = lrelu2(max2(acc[u*4+2], acc[u*4+3]));
        }
    }
    __syncthreads();

    // ---- L3: conv(16->32, k=5) + lrelu. lane = cout, task = (pr, 4 t's) ----
    for (int task = wrp; task < 30; task += 16) {
        int tg = task % 15, pr = task / 15;
        int t0 = 4 * tg;                           // conv t: t0..t0+3 (t<58)
        u64 acc[4];
        u64 bb = B3s[lane];
        acc[0] = acc[1] = acc[2] = acc[3] = bb;
        for (int ci = 0; ci < 16; ci++) {
            const u64* pb = P1 + pr * 1026 + ci * 64 + t0;
            u64 a[8];
#pragma unroll
            for (int j = 0; j < 8; j++) a[j] = pb[j];          // broadcast
            const float* wf = W3f + ci * 160 + lane;
            u64 w0 = dup2(wf[0]),  w1 = dup2(wf[32]), w2 = dup2(wf[64]);
            u64 w3 = dup2(wf[96]), w4 = dup2(wf[128]);
#pragma unroll
            for (int p = 0; p < 4; p++) {
                u64 s = acc[p];
                s = ffma2(a[p],     w0, s);
                s = ffma2(a[p + 1], w1, s);
                s = ffma2(a[p + 2], w2, s);
                s = ffma2(a[p + 3], w3, s);
                s = ffma2(a[p + 4], w4, s);
                acc[p] = s;
            }
        }
        u64* o = H3 + pr * 2050 + lane;
#pragma unroll
        for (int p = 0; p < 4; p++) {
            int t = t0 + p;
            if (t < 58) o[t * 32] = lrelu2(acc[p]);
        }
    }
    __syncthreads();

    // ---- L4: conv(32->32, k=5) + lrelu + pool. lane = cout -----------------
    for (int task = wrp; task < 28; task += 16) {
        int pg = task % 14, pr = task / 14;
        int t0 = 4 * pg;                           // conv t: t0..t0+3
        u64 acc[4];
        u64 bb = B4s[lane];
        acc[0] = acc[1] = acc[2] = acc[3] = bb;
        const u64* hb = H3 + pr * 2050;
        for (int ci = 0; ci < 32; ci++) {
            u64 a[8];
#pragma unroll
            for (int j = 0; j < 8; j++) a[j] = hb[(t0 + j) * 32 + ci]; // broadcast
            const float* wf = W4f + ci * 160 + lane;
            u64 w0 = dup2(wf[0]),  w1 = dup2(wf[32]), w2 = dup2(wf[64]);
            u64 w3 = dup2(wf[96]), w4 = dup2(wf[128]);
#pragma unroll
            for (int p = 0; p < 4; p++) {
                u64 s = acc[p];
                s = ffma2(a[p],     w0, s);
                s = ffma2(a[p + 1], w1, s);
                s = ffma2(a[p + 2], w2, s);
                s = ffma2(a[p + 3], w3, s);
                s = ffma2(a[p + 4], w4, s);
                acc[p] = s;
            }
        }
        int pq0 = 2 * pg;
        u64* o = P2 + pr * 866 + lane;
        o[pq0 * 32] = lrelu2(max2(acc[0], acc[1]));
        if (pq0 + 1 < 27)
            o[(pq0 + 1) * 32] = lrelu2(max2(acc[2], acc[3]));
    }
    __syncthreads();

    // ---- dense 864 -> 64: 512 threads = 64 oc x 8 chunks -------------------
    {
        int oc = tid & 63, chunk = tid >> 6;
        int j0 = chunk * 108;
        u64 acc[2] = {0ull, 0ull};
#pragma unroll 6
        for (int g = 0; g < 54; g++) {
            int idx = j0 + 2 * g;
            const float* wr = g_qwdP + idx * 64 + oc;
            u64 w0 = dup2(__ldg(wr));
            u64 w1 = dup2(__ldg(wr + 64));
#pragma unroll
            for (int q = 0; q < 2; q++) {
                ulonglong2 a = lds2(P2 + q * 866 + idx);
                acc[q] = ffma2(a.x, w0, acc[q]);
                acc[q] = ffma2(a.y, w1, acc[q]);
            }
        }
        PART[chunk * 128 + oc * 2 + 0] = acc[0];
        PART[chunk * 128 + oc * 2 + 1] = acc[1];
    }
    __syncthreads();

    // ---- reduce partials + bias + lrelu ------------------------------------
    if (tid < 128) {
        int oc = tid & 63, q = tid >> 6;
        u64 s = PART[oc * 2 + q];
#pragma unroll
        for (int c = 1; c < 8; c++) s = add2(s, PART[c * 128 + oc * 2 + q]);
        s = add2(s, BDs[oc]);
        HH[q * 64 + oc] = lrelu2(s);
    }
    __syncthreads();

    // ---- output 64 -> 1 ----------------------------------------------------
    if (tid < 64) {
        int q = tid >> 5, ln = tid & 31;
        float2 h0  = unpack2(HH[q * 64 + ln]);
        float2 h1v = unpack2(HH[q * 64 + 32 + ln]);
        float wl = g_qwo[ln], wh = g_qwo[ln + 32];
        float ax = h0.x * wl + h1v.x * wh;
        float ay = h0.y * wl + h1v.y * wh;
#pragma unroll
        for (int o = 16; o > 0; o >>= 1) {
            ax += __shfl_xor_sync(0xffffffffu, ax, o);
            ay += __shfl_xor_sync(0xffffffffu, ay, o);
        }
        if (ln == 0) {
            float bov = bo[0];
            reinterpret_cast<float2*>(out)[blockIdx.x * 2 + q] =
                make_float2(ax + bov, ay + bov);
        }
    }
}

// ---- launcher --------------------------------------------------------------
extern "C" void kernel_launch(void* const* d_in, const int* in_sizes, int n_in,
                              void* d_out, int out_size) {
    const float* x  = (const float*)d_in[0];
    const float* w1 = (const float*)d_in[1];
    const float* b1 = (const float*)d_in[2];
    const float* w2 = (const float*)d_in[3];
    const float* b2 = (const float*)d_in[4];
    const float* w3 = (const float*)d_in[5];
    const float* b3 = (const float*)d_in[6];
    const float* w4 = (const float*)d_in[7];
    const float* b4 = (const float*)d_in[8];
    const float* wd = (const float*)d_in[9];
    const float* bd = (const float*)d_in[10];
    const float* wo = (const float*)d_in[11];
    const float* bo = (const float*)d_in[12];

    cudaFuncSetAttribute(qcnn_kernel,
                         cudaFuncAttributeMaxDynamicSharedMemorySize, SMEM_BYTES);

    quant_prep_kernel<<<6, 256>>>(w1, w2, w3, w4, wd, wo);

    qcnn_kernel<<<8192, 512, SMEM_BYTES>>>(x, b1, b2, b3, b4, bd, bo,
                                           (float*)d_out);
}

// round 4
// speedup vs baseline: 1.9602x; 1.0478x over previous
#include <cuda_runtime.h>
#include <cuda_bf16.h>

// ----------------------------------------------------------------------------
// QCNN fused, f32x2 sample-pairs. Round 4: cut LDS wavefronts (was 95% L1):
// position-tile-8 in L3/L4, paired H3 layout (2 acts per uniform LDS.128),
// L2 restructured to 4-cout x 1-pos threads with minimum-bandwidth act loads.
// ----------------------------------------------------------------------------

typedef unsigned long long u64;

__device__ float g_qw1[64];
__device__ float g_qw2[768];
__device__ float g_qw3[2560];
__device__ float g_qw4[5120];
__device__ float g_qwdP[55296];   // permuted: [idx=pq*32+co][oc=64]
__device__ float g_qwo[64];

// ---- f32x2 helpers ---------------------------------------------------------
__device__ __forceinline__ u64 ffma2(u64 a, u64 b, u64 c) {
    u64 d;
    asm("fma.rn.f32x2 %0, %1, %2, %3;" : "=l"(d) : "l"(a), "l"(b), "l"(c));
    return d;
}
__device__ __forceinline__ u64 add2(u64 a, u64 b) {
    u64 d;
    asm("add.rn.f32x2 %0, %1, %2;" : "=l"(d) : "l"(a), "l"(b));
    return d;
}
__device__ __forceinline__ u64 pack2(float x, float y) {
    u64 d;
    asm("mov.b64 %0, {%1, %2};" : "=l"(d) : "f"(x), "f"(y));
    return d;
}
__device__ __forceinline__ float2 unpack2(u64 v) {
    float2 f;
    asm("mov.b64 {%0, %1}, %2;" : "=f"(f.x), "=f"(f.y) : "l"(v));
    return f;
}
__device__ __forceinline__ u64 dup2(float w) { return pack2(w, w); }
__device__ __forceinline__ u64 lrelu2(u64 v) {
    float2 f = unpack2(v);
    f.x = f.x > 0.0f ? f.x : 0.1f * f.x;
    f.y = f.y > 0.0f ? f.y : 0.1f * f.y;
    return pack2(f.x, f.y);
}
__device__ __forceinline__ u64 max2(u64 a, u64 b) {
    float2 fa = unpack2(a), fb = unpack2(b);
    return pack2(fmaxf(fa.x, fb.x), fmaxf(fa.y, fb.y));
}
__device__ __forceinline__ ulonglong2 lds2(const u64* p) {
    return *reinterpret_cast<const ulonglong2*>(p);
}

// ---- weight quantization prep ---------------------------------------------
__global__ void quant_prep_kernel(const float* __restrict__ w1,
                                  const float* __restrict__ w2,
                                  const float* __restrict__ w3,
                                  const float* __restrict__ w4,
                                  const float* __restrict__ wd,
                                  const float* __restrict__ wo) {
    __shared__ float red[256];
    int b = blockIdx.x, tid = threadIdx.x;
    const float* src; float* dst; int n; bool tr = false;
    if (b == 0)      { src = w1; dst = g_qw1;  n = 64; }
    else if (b == 1) { src = w2; dst = g_qw2;  n = 768; }
    else if (b == 2) { src = w3; dst = g_qw3;  n = 2560; }
    else if (b == 3) { src = w4; dst = g_qw4;  n = 5120; }
    else if (b == 4) { src = wd; dst = g_qwdP; n = 55296; tr = true; }
    else             { src = wo; dst = g_qwo;  n = 64; }

    float m = 0.0f;
    for (int i = tid; i < n; i += 256) m = fmaxf(m, fabsf(src[i]));
    red[tid] = m;
    __syncthreads();
    for (int s = 128; s > 0; s >>= 1) {
        if (tid < s) red[tid] = fmaxf(red[tid], red[tid + s]);
        __syncthreads();
    }
    float scale = red[0] / 127.0f;
    for (int i = tid; i < n; i += 256) {
        float q = rintf(src[i] / scale);           // round half-even == jnp.round
        q = fminf(fmaxf(q, -127.0f), 127.0f) * scale;
        if (tr) {
            int o = i / 864, j = i - o * 864;      // j = co*27 + pq
            int co = j / 27, pq = j - co * 27;
            dst[(pq * 32 + co) * 64 + o] = q;      // idx = pq*32+co
        } else dst[i] = q;
    }
}

// ---- fused network kernel --------------------------------------------------
// 512 threads, 4 samples (2 pairs) / block, 8192 blocks, 2 CTAs/SM.
//
// smem (u64):
//   SX   0     (2x258)    pr*258 + c*128 + t
//   H1   516   (2x2050)   pr*2050 + ci*128 + t
//   H3p  0     (2x1914)   pr*1914 + (t>>1)*66 + co*2 + (t&1)   (alias SX+H1)
//   P1   4616  (2x1026)   pr*1026 + ci*64 + p
//   P2   4616  (2x866)    pr*866 + pq*32 + co                  (alias P1)
//   W1   6668  (64, dup)
//   W2   6732  (1024, dup, k pad 4)
//   W3f  7756  (2560 floats)  [ci*5+k]*32 + co
//   W4f  9036  (5120 floats)  [ci*5+k]*32 + co
//   B*   11596..11756
//   PART 0 (1024), HH 1024 (128)   (alias dead H3p)
#define SMEM_U64 11756
#define SMEM_BYTES (SMEM_U64 * 8)

__global__ void __launch_bounds__(512, 2)
qcnn_kernel(const float* __restrict__ x,
            const float* __restrict__ b1, const float* __restrict__ b2,
            const float* __restrict__ b3, const float* __restrict__ b4,
            const float* __restrict__ bd, const float* __restrict__ bo,
            float* __restrict__ out) {
    extern __shared__ u64 sm[];
    const int tid  = threadIdx.x;
    const int wrp  = tid >> 5;
    const int lane = tid & 31;
    const int base = blockIdx.x * 4;

    u64* SX = sm;
    u64* H1 = sm + 516;
    u64* H3p = sm;
    u64* P1 = sm + 4616;
    u64* P2 = sm + 4616;
    u64* W1 = sm + 6668;
    u64* W2 = sm + 6732;
    float* W3f = (float*)(sm + 7756);
    float* W4f = (float*)(sm + 9036);
    u64* B1s = sm + 11596; u64* B2s = sm + 11612;
    u64* B3s = sm + 11628; u64* B4s = sm + 11660;
    u64* BDs = sm + 11692;
    u64* PART = sm;
    u64* HH   = sm + 1024;

    // ---- stage inputs + weights --------------------------------------------
    {
        int pr = tid >> 8, r = tid & 255;
        const float* xp = x + (base + 2 * pr) * 256 + r;
        SX[pr * 258 + r] = pack2(xp[0], xp[256]);
    }
    for (int i = tid; i < 64; i += 512) W1[i] = dup2(g_qw1[i]);
    for (int i = tid; i < 1024; i += 512) {
        int co = i >> 6, ci = (i >> 2) & 15, k = i & 3;
        W2[i] = dup2(k < 3 ? g_qw2[co * 48 + ci * 3 + k] : 0.0f);
    }
    for (int i = tid; i < 2560; i += 512) {
        int co = i & 31, r = i >> 5, ci = r / 5, k = r - ci * 5;
        W3f[i] = g_qw3[(co * 16 + ci) * 5 + k];
    }
    for (int i = tid; i < 5120; i += 512) {
        int co = i & 31, r = i >> 5, ci = r / 5, k = r - ci * 5;
        W4f[i] = g_qw4[(co * 32 + ci) * 5 + k];
    }
    if (tid < 16)                    { B1s[tid] = dup2(b1[tid]); B2s[tid] = dup2(b2[tid]); }
    else if (tid >= 32 && tid < 64)  { int q = tid - 32; B3s[q] = dup2(b3[q]); B4s[q] = dup2(b4[q]); }
    else if (tid >= 64 && tid < 128) { int q = tid - 64; BDs[q] = dup2(bd[q]); }
    __syncthreads();

    // ---- L1: conv(2->16, k=2) + lrelu, t = 0..126 --------------------------
    if (tid < 508) {
        int cg = tid & 1, pr = (tid >> 1) & 1, t = tid >> 2;
        const u64* xs = SX + pr * 258;
        u64 a00 = xs[t], a01 = xs[t + 1], a10 = xs[128 + t], a11 = xs[128 + t + 1];
        u64* o = H1 + pr * 2050 + t;
#pragma unroll
        for (int u = 0; u < 8; u++) {
            int co = cg * 8 + u;
            ulonglong2 w01 = lds2(W1 + co * 4);
            ulonglong2 w23 = lds2(W1 + co * 4 + 2);
            u64 acc = B1s[co];
            acc = ffma2(a00, w01.x, acc);
            acc = ffma2(a01, w01.y, acc);
            acc = ffma2(a10, w23.x, acc);
            acc = ffma2(a11, w23.y, acc);
            o[co * 128] = lrelu2(acc);
        }
    }
    __syncthreads();

    // ---- L2: conv(16->16, k=3) + lrelu + pool ------------------------------
    // thread = (cog[4 groups of 4 co], pr[2], pq[62]); 1 pooled pos, 4 couts.
    if (tid < 496) {
        int pq = tid % 62, r = tid / 62;
        int pr = r & 1, cog = r >> 1;
        const u64* hb = H1 + pr * 2050 + 2 * pq;
        u64 acc[8];
#pragma unroll
        for (int u = 0; u < 4; u++) {
            u64 b = B2s[cog * 4 + u];
            acc[u * 2] = acc[u * 2 + 1] = b;
        }
        for (int ci = 0; ci < 16; ci++) {
            const u64* h = hb + ci * 128;
            u64 a0 = h[0], a1 = h[1], a2 = h[2], a3 = h[3];
#pragma unroll
            for (int u = 0; u < 4; u++) {
                const u64* wp = W2 + ((cog * 4 + u) * 16 + ci) * 4;
                ulonglong2 w01 = lds2(wp), w23 = lds2(wp + 2);
                u64 s0 = acc[u * 2], s1 = acc[u * 2 + 1];
                s0 = ffma2(a0, w01.x, s0); s0 = ffma2(a1, w01.y, s0); s0 = ffma2(a2, w23.x, s0);
                s1 = ffma2(a1, w01.x, s1); s1 = ffma2(a2, w01.y, s1); s1 = ffma2(a3, w23.x, s1);
                acc[u * 2] = s0; acc[u * 2 + 1] = s1;
            }
        }
        u64* o = P1 + pr * 1026 + pq;
#pragma unroll
        for (int u = 0; u < 4; u++)
            o[(cog * 4 + u) * 64] = lrelu2(max2(acc[u * 2], acc[u * 2 + 1]));
    }
    __syncthreads();

    // ---- L3: conv(16->32, k=5) + lrelu. lane=cout, 16 tasks x 8 positions --
    {
        int tg = wrp & 7, pr = wrp >> 3;
        int t0 = 8 * tg;                            // conv t: t0..t0+7 (valid t<58)
        u64 acc[8];
        u64 bb = B3s[lane];
#pragma unroll
        for (int p = 0; p < 8; p++) acc[p] = bb;
        for (int ci = 0; ci < 16; ci++) {
            const u64* pb = P1 + pr * 1026 + ci * 64 + t0;
            u64 a[12];
#pragma unroll
            for (int j = 0; j < 6; j++) {           // 6 uniform LDS.128 broadcasts
                ulonglong2 v = lds2(pb + 2 * j);
                a[2 * j] = v.x; a[2 * j + 1] = v.y;
            }
            const float* wf = W3f + ci * 160 + lane;
            u64 w0 = dup2(wf[0]),  w1 = dup2(wf[32]), w2 = dup2(wf[64]);
            u64 w3 = dup2(wf[96]), w4 = dup2(wf[128]);
#pragma unroll
            for (int p = 0; p < 8; p++) {
                u64 s = acc[p];
                s = ffma2(a[p],     w0, s);
                s = ffma2(a[p + 1], w1, s);
                s = ffma2(a[p + 2], w2, s);
                s = ffma2(a[p + 3], w3, s);
                s = ffma2(a[p + 4], w4, s);
                acc[p] = s;
            }
        }
        u64* ob = H3p + pr * 1914 + lane * 2;
#pragma unroll
        for (int p = 0; p < 8; p++) {
            int t = t0 + p;
            if (t < 58) ob[(t >> 1) * 66 + (t & 1)] = lrelu2(acc[p]);
        }
    }
    __syncthreads();

    // ---- L4: conv(32->32, k=5) + lrelu + pool. lane=cout, 14 tasks ---------
    if (wrp < 14) {
        int pg = wrp % 7, pr = wrp / 7;
        int t0 = 8 * pg;                            // conv t: t0..t0+7 (valid t<54)
        u64 acc[8];
        u64 bb = B4s[lane];
#pragma unroll
        for (int p = 0; p < 8; p++) acc[p] = bb;
        const u64* hb = H3p + pr * 1914;
        int tp0 = 4 * pg;
        for (int ci = 0; ci < 32; ci++) {
            const u64* pb = hb + tp0 * 66 + ci * 2;
            u64 a[12];
#pragma unroll
            for (int j = 0; j < 6; j++) {           // 6 uniform LDS.128 broadcasts
                ulonglong2 v = lds2(pb + j * 66);
                a[2 * j] = v.x; a[2 * j + 1] = v.y;
            }
            const float* wf = W4f + ci * 160 + lane;
            u64 w0 = dup2(wf[0]),  w1 = dup2(wf[32]), w2 = dup2(wf[64]);
            u64 w3 = dup2(wf[96]), w4 = dup2(wf[128]);
#pragma unroll
            for (int p = 0; p < 8; p++) {
                u64 s = acc[p];
                s = ffma2(a[p],     w0, s);
                s = ffma2(a[p + 1], w1, s);
                s = ffma2(a[p + 2], w2, s);
                s = ffma2(a[p + 3], w3, s);
                s = ffma2(a[p + 4], w4, s);
                acc[p] = s;
            }
        }
        u64* ob = P2 + pr * 866 + lane;
#pragma unroll
        for (int q = 0; q < 4; q++) {
            int pq = 4 * pg + q;
            if (pq < 27)
                ob[pq * 32] = lrelu2(max2(acc[2 * q], acc[2 * q + 1]));
        }
    }
    __syncthreads();

    // ---- dense 864 -> 64: 512 threads = 64 oc x 8 chunks -------------------
    {
        int oc = tid & 63, chunk = tid >> 6;
        int j0 = chunk * 108;
        u64 acc[2] = {0ull, 0ull};
#pragma unroll 6
        for (int g = 0; g < 54; g++) {
            int idx = j0 + 2 * g;
            const float* wr = g_qwdP + idx * 64 + oc;
            u64 w0 = dup2(__ldg(wr));
            u64 w1 = dup2(__ldg(wr + 64));
#pragma unroll
            for (int q = 0; q < 2; q++) {
                ulonglong2 a = lds2(P2 + q * 866 + idx);
                acc[q] = ffma2(a.x, w0, acc[q]);
                acc[q] = ffma2(a.y, w1, acc[q]);
            }
        }
        PART[chunk * 128 + oc * 2 + 0] = acc[0];
        PART[chunk * 128 + oc * 2 + 1] = acc[1];
    }
    __syncthreads();

    // ---- reduce partials + bias + lrelu ------------------------------------
    if (tid < 128) {
        int oc = tid & 63, q = tid >> 6;
        u64 s = PART[oc * 2 + q];
#pragma unroll
        for (int c = 1; c < 8; c++) s = add2(s, PART[c * 128 + oc * 2 + q]);
        s = add2(s, BDs[oc]);
        HH[q * 64 + oc] = lrelu2(s);
    }
    __syncthreads();

    // ---- output 64 -> 1 ----------------------------------------------------
    if (tid < 64) {
        int q = tid >> 5, ln = tid & 31;
        float2 h0  = unpack2(HH[q * 64 + ln]);
        float2 h1v = unpack2(HH[q * 64 + 32 + ln]);
        float wl = g_qwo[ln], wh = g_qwo[ln + 32];
        float ax = h0.x * wl + h1v.x * wh;
        float ay = h0.y * wl + h1v.y * wh;
#pragma unroll
        for (int o = 16; o > 0; o >>= 1) {
            ax += __shfl_xor_sync(0xffffffffu, ax, o);
            ay += __shfl_xor_sync(0xffffffffu, ay, o);
        }
        if (ln == 0) {
            float bov = bo[0];
            reinterpret_cast<float2*>(out)[blockIdx.x * 2 + q] =
                make_float2(ax + bov, ay + bov);
        }
    }
}

// ---- launcher --------------------------------------------------------------
extern "C" void kernel_launch(void* const* d_in, const int* in_sizes, int n_in,
                              void* d_out, int out_size) {
    const float* x  = (const float*)d_in[0];
    const float* w1 = (const float*)d_in[1];
    const float* b1 = (const float*)d_in[2];
    const float* w2 = (const float*)d_in[3];
    const float* b2 = (const float*)d_in[4];
    const float* w3 = (const float*)d_in[5];
    const float* b3 = (const float*)d_in[6];
    const float* w4 = (const float*)d_in[7];
    const float* b4 = (const float*)d_in[8];
    const float* wd = (const float*)d_in[9];
    const float* bd = (const float*)d_in[10];
    const float* wo = (const float*)d_in[11];
    const float* bo = (const float*)d_in[12];

    cudaFuncSetAttribute(qcnn_kernel,
                         cudaFuncAttributeMaxDynamicSharedMemorySize, SMEM_BYTES);

    quant_prep_kernel<<<6, 256>>>(w1, w2, w3, w4, wd, wo);

    qcnn_kernel<<<8192, 512, SMEM_BYTES>>>(x, b1, b2, b3, b4, bd, bo,
                                           (float*)d_out);
}

// round 5
// speedup vs baseline: 2.3165x; 1.1818x over previous
#include <cuda_runtime.h>
#include <cuda_bf16.h>

// ----------------------------------------------------------------------------
// QCNN fused, f32x2 sample-pairs. Round 5: L2 switched to lane=cout broadcast
// pattern (was 4-wf strided loads), dense lanes cover 2 oc with paired weights,
// weights pre-transposed in prep so staging is float4 copies.
// ----------------------------------------------------------------------------

typedef unsigned long long u64;

__device__ __align__(16) float g_qw1[64];      // [co*4 + ci*2 + k]
__device__ __align__(16) float g_qw2[768];     // [(ci*3+k)*16 + co]
__device__ __align__(16) float g_qw3[2560];    // [(ci*5+k)*32 + co]
__device__ __align__(16) float g_qw4[5120];    // [(ci*5+k)*32 + co]
__device__ __align__(16) float g_qwd[55296];   // [idx=pq*32+co][oc*2+h] h:oc+32
__device__ __align__(16) float g_qwo[64];

// ---- f32x2 helpers ---------------------------------------------------------
__device__ __forceinline__ u64 ffma2(u64 a, u64 b, u64 c) {
    u64 d;
    asm("fma.rn.f32x2 %0, %1, %2, %3;" : "=l"(d) : "l"(a), "l"(b), "l"(c));
    return d;
}
__device__ __forceinline__ u64 add2(u64 a, u64 b) {
    u64 d;
    asm("add.rn.f32x2 %0, %1, %2;" : "=l"(d) : "l"(a), "l"(b));
    return d;
}
__device__ __forceinline__ u64 pack2(float x, float y) {
    u64 d;
    asm("mov.b64 %0, {%1, %2};" : "=l"(d) : "f"(x), "f"(y));
    return d;
}
__device__ __forceinline__ float2 unpack2(u64 v) {
    float2 f;
    asm("mov.b64 {%0, %1}, %2;" : "=f"(f.x), "=f"(f.y) : "l"(v));
    return f;
}
__device__ __forceinline__ u64 dup2(float w) { return pack2(w, w); }
__device__ __forceinline__ u64 lrelu2(u64 v) {
    float2 f = unpack2(v);
    f.x = f.x > 0.0f ? f.x : 0.1f * f.x;
    f.y = f.y > 0.0f ? f.y : 0.1f * f.y;
    return pack2(f.x, f.y);
}
__device__ __forceinline__ u64 max2(u64 a, u64 b) {
    float2 fa = unpack2(a), fb = unpack2(b);
    return pack2(fmaxf(fa.x, fb.x), fmaxf(fa.y, fb.y));
}
__device__ __forceinline__ ulonglong2 lds2(const u64* p) {
    return *reinterpret_cast<const ulonglong2*>(p);
}

// ---- weight quantization prep (writes kernel-ready layouts) ----------------
__global__ void quant_prep_kernel(const float* __restrict__ w1,
                                  const float* __restrict__ w2,
                                  const float* __restrict__ w3,
                                  const float* __restrict__ w4,
                                  const float* __restrict__ wd,
                                  const float* __restrict__ wo) {
    __shared__ float red[256];
    int b = blockIdx.x, tid = threadIdx.x;
    const float* src; float* dst; int n;
    if (b == 0)      { src = w1; dst = g_qw1; n = 64; }
    else if (b == 1) { src = w2; dst = g_qw2; n = 768; }
    else if (b == 2) { src = w3; dst = g_qw3; n = 2560; }
    else if (b == 3) { src = w4; dst = g_qw4; n = 5120; }
    else if (b == 4) { src = wd; dst = g_qwd; n = 55296; }
    else             { src = wo; dst = g_qwo; n = 64; }

    float m = 0.0f;
    for (int i = tid; i < n; i += 256) m = fmaxf(m, fabsf(src[i]));
    red[tid] = m;
    __syncthreads();
    for (int s = 128; s > 0; s >>= 1) {
        if (tid < s) red[tid] = fmaxf(red[tid], red[tid + s]);
        __syncthreads();
    }
    float scale = red[0] / 127.0f;
    for (int i = tid; i < n; i += 256) {
        float q = rintf(src[i] / scale);           // round half-even == jnp.round
        q = fminf(fmaxf(q, -127.0f), 127.0f) * scale;
        int di = i;
        if (b == 1) {               // [co=16][ci=16][k=3] -> [(ci*3+k)*16+co]
            int co = i / 48, r = i - co * 48, ci = r / 3, k = r - ci * 3;
            di = (ci * 3 + k) * 16 + co;
        } else if (b == 2) {        // [co=32][ci=16][k=5] -> [(ci*5+k)*32+co]
            int co = i / 80, r = i - co * 80, ci = r / 5, k = r - ci * 5;
            di = (ci * 5 + k) * 32 + co;
        } else if (b == 3) {        // [co=32][ci=32][k=5] -> [(ci*5+k)*32+co]
            int co = i / 160, r = i - co * 160, ci = r / 5, k = r - ci * 5;
            di = (ci * 5 + k) * 32 + co;
        } else if (b == 4) {        // [o=64][j=864] -> [idx][oc*2+h]
            int o = i / 864, j = i - o * 864;
            int co = j / 27, pq = j - co * 27;
            int idx = pq * 32 + co;
            int oc = o & 31, h = o >> 5;
            di = idx * 64 + oc * 2 + h;
        }
        dst[di] = q;
    }
}

// ---- fused network kernel --------------------------------------------------
// 512 threads, 4 samples (2 pairs)/block, 8192 blocks, 2 CTAs/SM.
//
// smem (u64):
//   SX   0      (2x258)   pr*258 + c*128 + t
//   H1   516    (2x2050)  pr*2050 + ci*128 + t
//   H3p  0      (2x1914)  pr*1914 + tp*66 + co*2 + (t&1)   (alias SX+H1)
//   P1   4616   (2x1120)  pr*1120 + ci*70 + p
//   P2   4616   (2x866)   pr*866 + pq*32 + co               (alias P1)
//   W1   6856   (64, dup u64)
//   W2f  6920   (768 floats = 384 u64)
//   W3f  7304   (2560 floats = 1280 u64)
//   W4f  8584   (5120 floats = 2560 u64)
//   B*   11144..11304
//   PART 0 (2048), HH 2048 (128)   (alias dead H3p)
#define SMEM_U64 11304
#define SMEM_BYTES (SMEM_U64 * 8)

__global__ void __launch_bounds__(512, 2)
qcnn_kernel(const float* __restrict__ x,
            const float* __restrict__ b1, const float* __restrict__ b2,
            const float* __restrict__ b3, const float* __restrict__ b4,
            const float* __restrict__ bd, const float* __restrict__ bo,
            float* __restrict__ out) {
    extern __shared__ u64 sm[];
    const int tid  = threadIdx.x;
    const int wrp  = tid >> 5;
    const int lane = tid & 31;
    const int base = blockIdx.x * 4;

    u64* SX  = sm;
    u64* H1  = sm + 516;
    u64* H3p = sm;
    u64* P1  = sm + 4616;
    u64* P2  = sm + 4616;
    u64* W1  = sm + 6856;
    float* W2f = (float*)(sm + 6920);
    float* W3f = (float*)(sm + 7304);
    float* W4f = (float*)(sm + 8584);
    u64* B1s = sm + 11144; u64* B2s = sm + 11160;
    u64* B3s = sm + 11176; u64* B4s = sm + 11208;
    u64* BDs = sm + 11240;
    u64* PART = sm;
    u64* HH   = sm + 2048;

    // ---- stage inputs + weights --------------------------------------------
    {
        int pr = tid >> 8, r = tid & 255;
        const float* xp = x + (base + 2 * pr) * 256 + r;
        SX[pr * 258 + r] = pack2(xp[0], xp[256]);
    }
    if (tid < 64) W1[tid] = dup2(g_qw1[tid]);
    for (int i = tid; i < 192;  i += 512) ((float4*)W2f)[i] = ((const float4*)g_qw2)[i];
    for (int i = tid; i < 640;  i += 512) ((float4*)W3f)[i] = ((const float4*)g_qw3)[i];
    for (int i = tid; i < 1280; i += 512) ((float4*)W4f)[i] = ((const float4*)g_qw4)[i];
    if (tid < 16)                    { B1s[tid] = dup2(b1[tid]); B2s[tid] = dup2(b2[tid]); }
    else if (tid >= 32 && tid < 64)  { int q = tid - 32; B3s[q] = dup2(b3[q]); B4s[q] = dup2(b4[q]); }
    else if (tid >= 64 && tid < 128) { int q = tid - 64; BDs[q] = dup2(bd[q]); }
    __syncthreads();

    // ---- L1: conv(2->16, k=2) + lrelu, t = 0..126 --------------------------
    if (tid < 508) {
        int cg = tid & 1, pr = (tid >> 1) & 1, t = tid >> 2;
        const u64* xs = SX + pr * 258;
        u64 a00 = xs[t], a01 = xs[t + 1], a10 = xs[128 + t], a11 = xs[128 + t + 1];
        u64* o = H1 + pr * 2050 + t;
#pragma unroll
        for (int u = 0; u < 8; u++) {
            int co = cg * 8 + u;
            ulonglong2 w01 = lds2(W1 + co * 4);
            ulonglong2 w23 = lds2(W1 + co * 4 + 2);
            u64 acc = B1s[co];
            acc = ffma2(a00, w01.x, acc);
            acc = ffma2(a01, w01.y, acc);
            acc = ffma2(a10, w23.x, acc);
            acc = ffma2(a11, w23.y, acc);
            o[co * 128] = lrelu2(acc);
        }
    }
    __syncthreads();

    // ---- L2: conv(16->16, k=3) + lrelu + pool. lane = (pr, co) -------------
    // 16 warps x 8 conv positions (= 4 pooled). pq0 = 4*warp.
    {
        int co = lane & 15, pr = lane >> 4;
        int pq0 = 4 * wrp;
        int t0c = 8 * wrp;                           // conv t: t0c..t0c+7
        u64 acc[8];
        u64 bb = B2s[co];
#pragma unroll
        for (int p = 0; p < 8; p++) acc[p] = bb;
        const u64* hb = H1 + pr * 2050 + t0c;
        for (int ci = 0; ci < 16; ci++) {
            const u64* h = hb + ci * 128;
            u64 a[10];
#pragma unroll
            for (int j = 0; j < 5; j++) {            // broadcast (2 addrs) lds2
                ulonglong2 v = lds2(h + 2 * j);
                a[2 * j] = v.x; a[2 * j + 1] = v.y;
            }
            const float* wf = W2f + ci * 48 + co;
            u64 w0 = dup2(wf[0]), w1 = dup2(wf[16]), w2 = dup2(wf[32]);
#pragma unroll
            for (int p = 0; p < 8; p++) {
                u64 s = acc[p];
                s = ffma2(a[p],     w0, s);
                s = ffma2(a[p + 1], w1, s);
                s = ffma2(a[p + 2], w2, s);
                acc[p] = s;
            }
        }
        u64* o = P1 + pr * 1120 + co * 70;
#pragma unroll
        for (int i = 0; i < 4; i++) {
            int pq = pq0 + i;
            if (pq < 62)
                o[pq] = lrelu2(max2(acc[2 * i], acc[2 * i + 1]));
        }
    }
    __syncthreads();

    // ---- L3: conv(16->32, k=5) + lrelu. lane=cout, 16 warps x 8 positions --
    {
        int tg = wrp & 7, pr = wrp >> 3;
        int t0 = 8 * tg;                             // conv t: t0..t0+7 (t<58)
        u64 acc[8];
        u64 bb = B3s[lane];
#pragma unroll
        for (int p = 0; p < 8; p++) acc[p] = bb;
        for (int ci = 0; ci < 16; ci++) {
            const u64* pb = P1 + pr * 1120 + ci * 70 + t0;
            u64 a[12];
#pragma unroll
            for (int j = 0; j < 6; j++) {            // uniform lds2 broadcasts
                ulonglong2 v = lds2(pb + 2 * j);
                a[2 * j] = v.x; a[2 * j + 1] = v.y;
            }
            const float* wf = W3f + ci * 160 + lane;
            u64 w0 = dup2(wf[0]),  w1 = dup2(wf[32]), w2 = dup2(wf[64]);
            u64 w3 = dup2(wf[96]), w4 = dup2(wf[128]);
#pragma unroll
            for (int p = 0; p < 8; p++) {
                u64 s = acc[p];
                s = ffma2(a[p],     w0, s);
                s = ffma2(a[p + 1], w1, s);
                s = ffma2(a[p + 2], w2, s);
                s = ffma2(a[p + 3], w3, s);
                s = ffma2(a[p + 4], w4, s);
                acc[p] = s;
            }
        }
        // pair-packed stores: tp = t>>1
        u64* ob = H3p + pr * 1914 + lane * 2;
#pragma unroll
        for (int i = 0; i < 4; i++) {
            int tp = 4 * tg + i;
            if (2 * tp < 58) {
                ulonglong2 v;
                v.x = lrelu2(acc[2 * i]);
                v.y = lrelu2(acc[2 * i + 1]);
                *reinterpret_cast<ulonglong2*>(ob + tp * 66) = v;
            }
        }
    }
    __syncthreads();

    // ---- L4: conv(32->32, k=5) + lrelu + pool. lane=cout, 14 warps ---------
    if (wrp < 14) {
        int pg = wrp % 7, pr = wrp / 7;
        u64 acc[8];
        u64 bb = B4s[lane];
#pragma unroll
        for (int p = 0; p < 8; p++) acc[p] = bb;
        const u64* hb = H3p + pr * 1914;
        int tp0 = 4 * pg;
        for (int ci = 0; ci < 32; ci++) {
            const u64* pb = hb + tp0 * 66 + ci * 2;
            u64 a[12];
#pragma unroll
            for (int j = 0; j < 6; j++) {            // uniform lds2 broadcasts
                ulonglong2 v = lds2(pb + j * 66);
                a[2 * j] = v.x; a[2 * j + 1] = v.y;
            }
            const float* wf = W4f + ci * 160 + lane;
            u64 w0 = dup2(wf[0]),  w1 = dup2(wf[32]), w2 = dup2(wf[64]);
            u64 w3 = dup2(wf[96]), w4 = dup2(wf[128]);
#pragma unroll
            for (int p = 0; p < 8; p++) {
                u64 s = acc[p];
                s = ffma2(a[p],     w0, s);
                s = ffma2(a[p + 1], w1, s);
                s = ffma2(a[p + 2], w2, s);
                s = ffma2(a[p + 3], w3, s);
                s = ffma2(a[p + 4], w4, s);
                acc[p] = s;
            }
        }
        u64* ob = P2 + pr * 866 + lane;
#pragma unroll
        for (int i = 0; i < 4; i++) {
            int pq = 4 * pg + i;
            if (pq < 27)
                ob[pq * 32] = lrelu2(max2(acc[2 * i], acc[2 * i + 1]));
        }
    }
    __syncthreads();

    // ---- dense 864 -> 64: 16 warps x 54-j chunks; lane = (oc, oc+32) -------
    {
        int j0 = wrp * 54;
        const float2* wdp = (const float2*)g_qwd;    // [idx][oc] = (w_oc, w_oc+32)
        u64 acc[4] = {0ull, 0ull, 0ull, 0ull};       // [q*2 + h]
#pragma unroll 3
        for (int g = 0; g < 27; g++) {
            int j = j0 + 2 * g;
            float2 wa = __ldg(wdp + j * 32 + lane);
            float2 wb = __ldg(wdp + (j + 1) * 32 + lane);
            u64 w0a = dup2(wa.x), w0b = dup2(wa.y);
            u64 w1a = dup2(wb.x), w1b = dup2(wb.y);
#pragma unroll
            for (int q = 0; q < 2; q++) {
                ulonglong2 a = lds2(P2 + q * 866 + j);
                acc[q*2]   = ffma2(a.x, w0a, acc[q*2]);
                acc[q*2]   = ffma2(a.y, w1a, acc[q*2]);
                acc[q*2+1] = ffma2(a.x, w0b, acc[q*2+1]);
                acc[q*2+1] = ffma2(a.y, w1b, acc[q*2+1]);
            }
        }
        u64* pb = PART + wrp * 128;
#pragma unroll
        for (int q = 0; q < 2; q++) {
            pb[lane * 2 + q]        = acc[q*2];
            pb[(lane + 32) * 2 + q] = acc[q*2+1];
        }
    }
    __syncthreads();

    // ---- reduce 16 chunks + bias + lrelu -----------------------------------
    if (tid < 128) {
        int oc = tid & 63, q = tid >> 6;
        u64 s = PART[oc * 2 + q];
#pragma unroll
        for (int c = 1; c < 16; c++) s = add2(s, PART[c * 128 + oc * 2 + q]);
        s = add2(s, BDs[oc]);
        HH[q * 64 + oc] = lrelu2(s);
    }
    __syncthreads();

    // ---- output 64 -> 1 ----------------------------------------------------
    if (tid < 64) {
        int q = tid >> 5, ln = tid & 31;
        float2 h0  = unpack2(HH[q * 64 + ln]);
        float2 h1v = unpack2(HH[q * 64 + 32 + ln]);
        float wl = g_qwo[ln], wh = g_qwo[ln + 32];
        float ax = h0.x * wl + h1v.x * wh;
        float ay = h0.y * wl + h1v.y * wh;
#pragma unroll
        for (int o = 16; o > 0; o >>= 1) {
            ax += __shfl_xor_sync(0xffffffffu, ax, o);
            ay += __shfl_xor_sync(0xffffffffu, ay, o);
        }
        if (ln == 0) {
            float bov = bo[0];
            reinterpret_cast<float2*>(out)[blockIdx.x * 2 + q] =
                make_float2(ax + bov, ay + bov);
        }
    }
}

// ---- launcher --------------------------------------------------------------
extern "C" void kernel_launch(void* const* d_in, const int* in_sizes, int n_in,
                              void* d_out, int out_size) {
    const float* x  = (const float*)d_in[0];
    const float* w1 = (const float*)d_in[1];
    const float* b1 = (const float*)d_in[2];
    const float* w2 = (const float*)d_in[3];
    const float* b2 = (const float*)d_in[4];
    const float* w3 = (const float*)d_in[5];
    const float* b3 = (const float*)d_in[6];
    const float* w4 = (const float*)d_in[7];
    const float* b4 = (const float*)d_in[8];
    const float* wd = (const float*)d_in[9];
    const float* bd = (const float*)d_in[10];
    const float* wo = (const float*)d_in[11];
    const float* bo = (const float*)d_in[12];

    cudaFuncSetAttribute(qcnn_kernel,
                         cudaFuncAttributeMaxDynamicSharedMemorySize, SMEM_BYTES);

    quant_prep_kernel<<<6, 256>>>(w1, w2, w3, w4, wd, wo);

    qcnn_kernel<<<8192, 512, SMEM_BYTES>>>(x, b1, b2, b3, b4, bd, bo,
                                           (float*)d_out);
}

// round 6
// speedup vs baseline: 2.3977x; 1.0351x over previous
#include <cuda_runtime.h>
#include <cuda_bf16.h>

// ----------------------------------------------------------------------------
// QCNN, round 6: two-kernel split.
//   conv kernel: 256 thr, 1 sample-pair, 4 CTAs/SM, L1..L4 fused, P2 -> global
//   dense kernel: 256 thr, 4 pairs (8 samples), dense weights amortized 2x
// ----------------------------------------------------------------------------

typedef unsigned long long u64;

__device__ __align__(16) float g_qw1[64];      // [co*4 + ci*2 + k]
__device__ __align__(16) float g_qw2[768];     // [(ci*3+k)*16 + co]
__device__ __align__(16) float g_qw3[2560];    // [(ci*5+k)*32 + co]
__device__ __align__(16) float g_qw4[5120];    // [(ci*5+k)*32 + co]
__device__ __align__(16) float g_qwd[55296];   // [idx=pq*32+co][oc*2+h]  h: +32
__device__ __align__(16) float g_qwo[64];
__device__ __align__(16) u64   g_P2[16384 * 864];  // [pair][pq*32+co] f32x2

// ---- f32x2 helpers ---------------------------------------------------------
__device__ __forceinline__ u64 ffma2(u64 a, u64 b, u64 c) {
    u64 d;
    asm("fma.rn.f32x2 %0, %1, %2, %3;" : "=l"(d) : "l"(a), "l"(b), "l"(c));
    return d;
}
__device__ __forceinline__ u64 add2(u64 a, u64 b) {
    u64 d;
    asm("add.rn.f32x2 %0, %1, %2;" : "=l"(d) : "l"(a), "l"(b));
    return d;
}
__device__ __forceinline__ u64 pack2(float x, float y) {
    u64 d;
    asm("mov.b64 %0, {%1, %2};" : "=l"(d) : "f"(x), "f"(y));
    return d;
}
__device__ __forceinline__ float2 unpack2(u64 v) {
    float2 f;
    asm("mov.b64 {%0, %1}, %2;" : "=f"(f.x), "=f"(f.y) : "l"(v));
    return f;
}
__device__ __forceinline__ u64 dup2(float w) { return pack2(w, w); }
__device__ __forceinline__ u64 lrelu2(u64 v) {
    float2 f = unpack2(v);
    f.x = f.x > 0.0f ? f.x : 0.1f * f.x;
    f.y = f.y > 0.0f ? f.y : 0.1f * f.y;
    return pack2(f.x, f.y);
}
__device__ __forceinline__ u64 max2(u64 a, u64 b) {
    float2 fa = unpack2(a), fb = unpack2(b);
    return pack2(fmaxf(fa.x, fb.x), fmaxf(fa.y, fb.y));
}
__device__ __forceinline__ ulonglong2 lds2(const u64* p) {
    return *reinterpret_cast<const ulonglong2*>(p);
}

// ---- weight quantization prep ---------------------------------------------
__global__ void quant_prep_kernel(const float* __restrict__ w1,
                                  const float* __restrict__ w2,
                                  const float* __restrict__ w3,
                                  const float* __restrict__ w4,
                                  const float* __restrict__ wd,
                                  const float* __restrict__ wo) {
    __shared__ float red[256];
    int b = blockIdx.x, tid = threadIdx.x;
    const float* src; float* dst; int n;
    if (b == 0)      { src = w1; dst = g_qw1; n = 64; }
    else if (b == 1) { src = w2; dst = g_qw2; n = 768; }
    else if (b == 2) { src = w3; dst = g_qw3; n = 2560; }
    else if (b == 3) { src = w4; dst = g_qw4; n = 5120; }
    else if (b == 4) { src = wd; dst = g_qwd; n = 55296; }
    else             { src = wo; dst = g_qwo; n = 64; }

    float m = 0.0f;
    for (int i = tid; i < n; i += 256) m = fmaxf(m, fabsf(src[i]));
    red[tid] = m;
    __syncthreads();
    for (int s = 128; s > 0; s >>= 1) {
        if (tid < s) red[tid] = fmaxf(red[tid], red[tid + s]);
        __syncthreads();
    }
    float scale = red[0] / 127.0f;
    for (int i = tid; i < n; i += 256) {
        float q = rintf(src[i] / scale);           // round half-even == jnp.round
        q = fminf(fmaxf(q, -127.0f), 127.0f) * scale;
        int di = i;
        if (b == 1) {
            int co = i / 48, r = i - co * 48, ci = r / 3, k = r - ci * 3;
            di = (ci * 3 + k) * 16 + co;
        } else if (b == 2) {
            int co = i / 80, r = i - co * 80, ci = r / 5, k = r - ci * 5;
            di = (ci * 5 + k) * 32 + co;
        } else if (b == 3) {
            int co = i / 160, r = i - co * 160, ci = r / 5, k = r - ci * 5;
            di = (ci * 5 + k) * 32 + co;
        } else if (b == 4) {
            int o = i / 864, j = i - o * 864;
            int co = j / 27, pq = j - co * 27;
            int idx = pq * 32 + co;
            int oc = o & 31, h = o >> 5;
            di = idx * 64 + oc * 2 + h;
        }
        dst[di] = q;
    }
}

// ---- conv kernel: L1..L4 for one sample-pair -------------------------------
// smem (u64):
//   A:    [0, 2052)    H1 [ci*128+t] then H3p [tp*66 + co*2 + par] (alias)
//   P1:   [2052, 3140) [ci*68 + p]; staging aliases: SX@2052(258),
//                      W1s@2310(64 dup), B1s@2374(16)
//   W3f:  [3140, 4420) 2560 floats [(ci*5+k)*32+co]
//   W4f:  [4420, 6980) 5120 floats [(ci*5+k)*32+co]
//   B2s:  [6980,6996) B3s:[6996,7028) B4s:[7028,7060)
#define CONV_SMEM_U64 7060
#define CONV_SMEM_BYTES (CONV_SMEM_U64 * 8)

__global__ void __launch_bounds__(256, 4)
conv_kernel(const float* __restrict__ x,
            const float* __restrict__ b1, const float* __restrict__ b2,
            const float* __restrict__ b3, const float* __restrict__ b4) {
    extern __shared__ u64 sm[];
    const int tid  = threadIdx.x;
    const int wrp  = tid >> 5;
    const int lane = tid & 31;
    const int pair = blockIdx.x;

    u64* H1  = sm;
    u64* H3p = sm;
    u64* P1  = sm + 2052;
    u64* SX  = sm + 2052;
    u64* W1s = sm + 2310;
    u64* B1s = sm + 2374;
    float* W3f = (float*)(sm + 3140);
    float* W4f = (float*)(sm + 4420);
    u64* B2s = sm + 6980;
    u64* B3s = sm + 6996;
    u64* B4s = sm + 7028;

    // ---- stage -------------------------------------------------------------
    {
        int c = tid >> 7, t = tid & 127;
        const float* xp = x + pair * 512 + c * 128 + t;
        SX[c * 128 + t] = pack2(xp[0], xp[256]);    // samples 2p, 2p+1
    }
    for (int i = tid; i < 640;  i += 256) ((float4*)W3f)[i] = ((const float4*)g_qw3)[i];
    for (int i = tid; i < 1280; i += 256) ((float4*)W4f)[i] = ((const float4*)g_qw4)[i];
    if (tid < 64) W1s[tid] = dup2(g_qw1[tid]);
    else if (tid >= 64 && tid < 80)   B1s[tid - 64] = dup2(b1[tid - 64]);
    else if (tid >= 96 && tid < 112)  B2s[tid - 96] = dup2(b2[tid - 96]);
    else if (tid >= 128 && tid < 160) B3s[tid - 128] = dup2(b3[tid - 128]);
    else if (tid >= 160 && tid < 192) B4s[tid - 160] = dup2(b4[tid - 160]);
    __syncthreads();

    // ---- L1: conv(2->16, k=2) + lrelu, t = 0..126 --------------------------
    if (tid < 254) {
        int cg = tid & 1, t = tid >> 1;
        u64 a00 = SX[t], a01 = SX[t + 1], a10 = SX[128 + t], a11 = SX[128 + t + 1];
        u64* o = H1 + t;
#pragma unroll
        for (int u = 0; u < 8; u++) {
            int co = cg * 8 + u;
            ulonglong2 w01 = lds2(W1s + co * 4);
            ulonglong2 w23 = lds2(W1s + co * 4 + 2);
            u64 acc = B1s[co];
            acc = ffma2(a00, w01.x, acc);
            acc = ffma2(a01, w01.y, acc);
            acc = ffma2(a10, w23.x, acc);
            acc = ffma2(a11, w23.y, acc);
            o[co * 128] = lrelu2(acc);
        }
    }
    __syncthreads();

    // ---- L2: conv(16->16, k=3) + lrelu + pool ------------------------------
    // warp = 8 pooled (16 conv); lane = (co16, half2): half picks 8-conv span.
    {
        int co = lane & 15, half = lane >> 4;
        int t0 = 16 * wrp + 8 * half;               // conv window start
        u64 acc[8];
        u64 bb = B2s[co];
#pragma unroll
        for (int p = 0; p < 8; p++) acc[p] = bb;
        for (int ci = 0; ci < 16; ci++) {
            const u64* h = H1 + ci * 128 + t0;
            u64 a[10];
#pragma unroll
            for (int s = 0; s < 5; s++) {           // 2-addr lds2 (per half)
                ulonglong2 v = lds2(h + 2 * s);
                a[2 * s] = v.x; a[2 * s + 1] = v.y;
            }
            u64 w0 = dup2(__ldg(g_qw2 + (ci * 3 + 0) * 16 + co));
            u64 w1 = dup2(__ldg(g_qw2 + (ci * 3 + 1) * 16 + co));
            u64 w2 = dup2(__ldg(g_qw2 + (ci * 3 + 2) * 16 + co));
#pragma unroll
            for (int p = 0; p < 8; p++) {
                u64 s = acc[p];
                s = ffma2(a[p],     w0, s);
                s = ffma2(a[p + 1], w1, s);
                s = ffma2(a[p + 2], w2, s);
                acc[p] = s;
            }
        }
        u64* o = P1 + co * 68;
#pragma unroll
        for (int i = 0; i < 4; i++) {
            int pq = 8 * wrp + 4 * half + i;
            if (pq < 62)
                o[pq] = lrelu2(max2(acc[2 * i], acc[2 * i + 1]));
        }
    }
    __syncthreads();

    // ---- L3: conv(16->32, k=5) + lrelu. lane = cout, 8 warps x 8 pos -------
    {
        int t0 = 8 * wrp;                           // conv t: t0..t0+7 (t<58)
        u64 acc[8];
        u64 bb = B3s[lane];
#pragma unroll
        for (int p = 0; p < 8; p++) acc[p] = bb;
        for (int ci = 0; ci < 16; ci++) {
            const u64* pb = P1 + ci * 68 + t0;
            u64 a[12];
#pragma unroll
            for (int j = 0; j < 6; j++) {           // uniform lds2 broadcasts
                ulonglong2 v = lds2(pb + 2 * j);
                a[2 * j] = v.x; a[2 * j + 1] = v.y;
            }
            const float* wf = W3f + ci * 160 + lane;
            u64 w0 = dup2(wf[0]),  w1 = dup2(wf[32]), w2 = dup2(wf[64]);
            u64 w3 = dup2(wf[96]), w4 = dup2(wf[128]);
#pragma unroll
            for (int p = 0; p < 8; p++) {
                u64 s = acc[p];
                s = ffma2(a[p],     w0, s);
                s = ffma2(a[p + 1], w1, s);
                s = ffma2(a[p + 2], w2, s);
                s = ffma2(a[p + 3], w3, s);
                s = ffma2(a[p + 4], w4, s);
                acc[p] = s;
            }
        }
        u64* ob = H3p + lane * 2;
#pragma unroll
        for (int i = 0; i < 4; i++) {
            int tp = 4 * wrp + i;
            if (tp < 29) {                          // 2tp < 58
                ulonglong2 v;
                v.x = lrelu2(acc[2 * i]);
                v.y = lrelu2(acc[2 * i + 1]);
                *reinterpret_cast<ulonglong2*>(ob + tp * 66) = v;
            }
        }
    }
    __syncthreads();

    // ---- L4: conv(32->32, k=5) + lrelu + pool -> global P2 -----------------
    if (wrp < 7) {
        int tp0 = 4 * wrp;                          // conv t0 = 8*wrp
        u64 acc[8];
        u64 bb = B4s[lane];
#pragma unroll
        for (int p = 0; p < 8; p++) acc[p] = bb;
        for (int ci = 0; ci < 32; ci++) {
            const u64* pb = H3p + tp0 * 66 + ci * 2;
            u64 a[12];
#pragma unroll
            for (int j = 0; j < 6; j++) {           // uniform lds2 broadcasts
                ulonglong2 v = lds2(pb + j * 66);
                a[2 * j] = v.x; a[2 * j + 1] = v.y;
            }
            const float* wf = W4f + ci * 160 + lane;
            u64 w0 = dup2(wf[0]),  w1 = dup2(wf[32]), w2 = dup2(wf[64]);
            u64 w3 = dup2(wf[96]), w4 = dup2(wf[128]);
#pragma unroll
            for (int p = 0; p < 8; p++) {
                u64 s = acc[p];
                s = ffma2(a[p],     w0, s);
                s = ffma2(a[p + 1], w1, s);
                s = ffma2(a[p + 2], w2, s);
                s = ffma2(a[p + 3], w3, s);
                s = ffma2(a[p + 4], w4, s);
                acc[p] = s;
            }
        }
        u64* ob = g_P2 + pair * 864 + lane;
#pragma unroll
        for (int i = 0; i < 4; i++) {
            int pq = 4 * wrp + i;
            if (pq < 27)
                ob[pq * 32] = lrelu2(max2(acc[2 * i], acc[2 * i + 1]));
        }
    }
}

// ---- dense kernel: 864->64->1 for 4 pairs (8 samples) ----------------------
// smem (u64): SP2 [0,3456) [q*864+j]; PART [3456,5504); HH [5504,5760)
#define DENSE_SMEM_U64 5760
#define DENSE_SMEM_BYTES (DENSE_SMEM_U64 * 8)

__global__ void __launch_bounds__(256)
dense_kernel(const float* __restrict__ bd, const float* __restrict__ bo,
             float* __restrict__ out) {
    extern __shared__ u64 sm[];
    const int tid  = threadIdx.x;
    const int wrp  = tid >> 5;
    const int lane = tid & 31;
    const int blk  = blockIdx.x;

    u64* SP2  = sm;
    u64* PART = sm + 3456;
    u64* HH   = sm + 5504;

    // stage 4 pairs of P2 rows
    for (int i = tid; i < 1728; i += 256) {
        int q = i / 432, r = i - q * 432;
        ulonglong2 v = *((const ulonglong2*)(g_P2 + (blk * 4 + q) * 864) + r);
        *reinterpret_cast<ulonglong2*>(SP2 + q * 864 + 2 * r) = v;
    }
    __syncthreads();

    // 8 warps x 108-j chunks; lane covers (oc, oc+32) for 4 pairs
    {
        int j0 = wrp * 108;
        const float2* wdp = (const float2*)g_qwd;   // [idx][oc] = (w_oc, w_oc+32)
        u64 acc[8] = {0, 0, 0, 0, 0, 0, 0, 0};      // [q*2 + h]
#pragma unroll 3
        for (int g = 0; g < 54; g++) {
            int j = j0 + 2 * g;
            float2 wa = __ldg(wdp + j * 32 + lane);
            float2 wb = __ldg(wdp + (j + 1) * 32 + lane);
            u64 w0a = dup2(wa.x), w0b = dup2(wa.y);
            u64 w1a = dup2(wb.x), w1b = dup2(wb.y);
#pragma unroll
            for (int q = 0; q < 4; q++) {
                ulonglong2 a = lds2(SP2 + q * 864 + j);
                acc[q*2]   = ffma2(a.x, w0a, acc[q*2]);
                acc[q*2]   = ffma2(a.y, w1a, acc[q*2]);
                acc[q*2+1] = ffma2(a.x, w0b, acc[q*2+1]);
                acc[q*2+1] = ffma2(a.y, w1b, acc[q*2+1]);
            }
        }
        u64* pb = PART + wrp * 256;
#pragma unroll
        for (int q = 0; q < 4; q++) {
            pb[lane * 4 + q]        = acc[q*2];
            pb[(lane + 32) * 4 + q] = acc[q*2+1];
        }
    }
    __syncthreads();

    // reduce 8 chunks + bias + lrelu
    {
        int oc = tid & 63, q = tid >> 6;
        u64 s = PART[oc * 4 + q];
#pragma unroll
        for (int c = 1; c < 8; c++) s = add2(s, PART[c * 256 + oc * 4 + q]);
        s = add2(s, dup2(bd[oc]));
        HH[q * 64 + oc] = lrelu2(s);
    }
    __syncthreads();

    // output 64 -> 1
    if (tid < 128) {
        int q = tid >> 5, ln = tid & 31;
        float2 h0  = unpack2(HH[q * 64 + ln]);
        float2 h1v = unpack2(HH[q * 64 + 32 + ln]);
        float wl = g_qwo[ln], wh = g_qwo[ln + 32];
        float ax = h0.x * wl + h1v.x * wh;
        float ay = h0.y * wl + h1v.y * wh;
#pragma unroll
        for (int o = 16; o > 0; o >>= 1) {
            ax += __shfl_xor_sync(0xffffffffu, ax, o);
            ay += __shfl_xor_sync(0xffffffffu, ay, o);
        }
        if (ln == 0) {
            float bov = bo[0];
            reinterpret_cast<float2*>(out)[blk * 4 + q] =
                make_float2(ax + bov, ay + bov);
        }
    }
}

// ---- launcher --------------------------------------------------------------
extern "C" void kernel_launch(void* const* d_in, const int* in_sizes, int n_in,
                              void* d_out, int out_size) {
    const float* x  = (const float*)d_in[0];
    const float* w1 = (const float*)d_in[1];
    const float* b1 = (const float*)d_in[2];
    const float* w2 = (const float*)d_in[3];
    const float* b2 = (const float*)d_in[4];
    const float* w3 = (const float*)d_in[5];
    const float* b3 = (const float*)d_in[6];
    const float* w4 = (const float*)d_in[7];
    const float* b4 = (const float*)d_in[8];
    const float* wd = (const float*)d_in[9];
    const float* bd = (const float*)d_in[10];
    const float* wo = (const float*)d_in[11];
    const float* bo = (const float*)d_in[12];

    cudaFuncSetAttribute(conv_kernel,
                         cudaFuncAttributeMaxDynamicSharedMemorySize, CONV_SMEM_BYTES);
    cudaFuncSetAttribute(dense_kernel,
                         cudaFuncAttributeMaxDynamicSharedMemorySize, DENSE_SMEM_BYTES);

    quant_prep_kernel<<<6, 256>>>(w1, w2, w3, w4, wd, wo);
    conv_kernel<<<16384, 256, CONV_SMEM_BYTES>>>(x, b1, b2, b3, b4);
    dense_kernel<<<4096, 256, DENSE_SMEM_BYTES>>>(bd, bo, (float*)d_out);
}

// round 9
// speedup vs baseline: 2.5118x; 1.0476x over previous
#include <cuda_runtime.h>
#include <cuda_bf16.h>

// ----------------------------------------------------------------------------
// QCNN, round 7: two-phase parallel prep (was 77us serial), dense amortized to
// 16 samples/block (halves L2 weight traffic). Conv kernel unchanged.
// ----------------------------------------------------------------------------

typedef unsigned long long u64;

__device__ __align__(16) float g_qw1[64];      // [co*4 + ci*2 + k]
__device__ __align__(16) float g_qw2[768];     // [(ci*3+k)*16 + co]
__device__ __align__(16) float g_qw3[2560];    // [(ci*5+k)*32 + co]
__device__ __align__(16) float g_qw4[5120];    // [(ci*5+k)*32 + co]
__device__ __align__(16) float g_qwd[55296];   // [idx=pq*32+co][oc*2+h]  h: +32
__device__ __align__(16) float g_qwo[64];
__device__ float g_scale[6];
__device__ __align__(16) u64   g_P2[16384 * 864];  // [pair][pq*32+co] f32x2

// ---- f32x2 helpers ---------------------------------------------------------
__device__ __forceinline__ u64 ffma2(u64 a, u64 b, u64 c) {
    u64 d;
    asm("fma.rn.f32x2 %0, %1, %2, %3;" : "=l"(d) : "l"(a), "l"(b), "l"(c));
    return d;
}
__device__ __forceinline__ u64 add2(u64 a, u64 b) {
    u64 d;
    asm("add.rn.f32x2 %0, %1, %2;" : "=l"(d) : "l"(a), "l"(b));
    return d;
}
__device__ __forceinline__ u64 pack2(float x, float y) {
    u64 d;
    asm("mov.b64 %0, {%1, %2};" : "=l"(d) : "f"(x), "f"(y));
    return d;
}
__device__ __forceinline__ float2 unpack2(u64 v) {
    float2 f;
    asm("mov.b64 {%0, %1}, %2;" : "=f"(f.x), "=f"(f.y) : "l"(v));
    return f;
}
__device__ __forceinline__ u64 dup2(float w) { return pack2(w, w); }
__device__ __forceinline__ u64 lrelu2(u64 v) {
    float2 f = unpack2(v);
    f.x = f.x > 0.0f ? f.x : 0.1f * f.x;
    f.y = f.y > 0.0f ? f.y : 0.1f * f.y;
    return pack2(f.x, f.y);
}
__device__ __forceinline__ u64 max2(u64 a, u64 b) {
    float2 fa = unpack2(a), fb = unpack2(b);
    return pack2(fmaxf(fa.x, fb.x), fmaxf(fa.y, fb.y));
}
__device__ __forceinline__ ulonglong2 lds2(const u64* p) {
    return *reinterpret_cast<const ulonglong2*>(p);
}

// ---- prep phase A: per-tensor scale (max|w| / 127) -------------------------
__global__ void scale_kernel(const float* __restrict__ w1,
                             const float* __restrict__ w2,
                             const float* __restrict__ w3,
                             const float* __restrict__ w4,
                             const float* __restrict__ wd,
                             const float* __restrict__ wo) {
    __shared__ float red[256];
    int b = blockIdx.x, tid = threadIdx.x;
    const float* src; int n;
    if (b == 0)      { src = w1; n = 64; }
    else if (b == 1) { src = w2; n = 768; }
    else if (b == 2) { src = w3; n = 2560; }
    else if (b == 3) { src = w4; n = 5120; }
    else if (b == 4) { src = wd; n = 55296; }
    else             { src = wo; n = 64; }
    float m = 0.0f;
    for (int i = tid; i < n; i += 256) m = fmaxf(m, fabsf(src[i]));
    red[tid] = m;
    __syncthreads();
    for (int s = 128; s > 0; s >>= 1) {
        if (tid < s) red[tid] = fmaxf(red[tid], red[tid + s]);
        __syncthreads();
    }
    if (tid == 0) g_scale[b] = red[0] / 127.0f;
}

// ---- prep phase B: quantize + permute, fully parallel ----------------------
// block ranges: w1[0,1) w2[1,4) w3[4,14) w4[14,34) wd[34,250) wo[250,251)
__global__ void quantize_kernel(const float* __restrict__ w1,
                                const float* __restrict__ w2,
                                const float* __restrict__ w3,
                                const float* __restrict__ w4,
                                const float* __restrict__ wd,
                                const float* __restrict__ wo) {
    int blk = blockIdx.x, tid = threadIdx.x;
    int b, i;
    const float* src; float* dst; int n;
    if (blk < 1)        { b = 0; src = w1; dst = g_qw1; n = 64;    i = blk * 256 + tid; }
    else if (blk < 4)   { b = 1; src = w2; dst = g_qw2; n = 768;   i = (blk - 1) * 256 + tid; }
    else if (blk < 14)  { b = 2; src = w3; dst = g_qw3; n = 2560;  i = (blk - 4) * 256 + tid; }
    else if (blk < 34)  { b = 3; src = w4; dst = g_qw4; n = 5120;  i = (blk - 14) * 256 + tid; }
    else if (blk < 250) { b = 4; src = wd; dst = g_qwd; n = 55296; i = (blk - 34) * 256 + tid; }
    else                { b = 5; src = wo; dst = g_qwo; n = 64;    i = (blk - 250) * 256 + tid; }
    if (i >= n) return;
    float scale = g_scale[b];
    float q = rintf(src[i] / scale);               // round half-even == jnp.round
    q = fminf(fmaxf(q, -127.0f), 127.0f) * scale;
    int di = i;
    if (b == 1) {
        int co = i / 48, r = i - co * 48, ci = r / 3, k = r - ci * 3;
        di = (ci * 3 + k) * 16 + co;
    } else if (b == 2) {
        int co = i / 80, r = i - co * 80, ci = r / 5, k = r - ci * 5;
        di = (ci * 5 + k) * 32 + co;
    } else if (b == 3) {
        int co = i / 160, r = i - co * 160, ci = r / 5, k = r - ci * 5;
        di = (ci * 5 + k) * 32 + co;
    } else if (b == 4) {
        int o = i / 864, j = i - o * 864;
        int co = j / 27, pq = j - co * 27;
        int idx = pq * 32 + co;
        int oc = o & 31, h = o >> 5;
        di = idx * 64 + oc * 2 + h;
    }
    dst[di] = q;
}

// ---- conv kernel: L1..L4 for one sample-pair (unchanged from round 6) ------
#define CONV_SMEM_U64 7060
#define CONV_SMEM_BYTES (CONV_SMEM_U64 * 8)

__global__ void __launch_bounds__(256, 4)
conv_kernel(const float* __restrict__ x,
            const float* __restrict__ b1, const float* __restrict__ b2,
            const float* __restrict__ b3, const float* __restrict__ b4) {
    extern __shared__ u64 sm[];
    const int tid  = threadIdx.x;
    const int wrp  = tid >> 5;
    const int lane = tid & 31;
    const int pair = blockIdx.x;

    u64* H1  = sm;
    u64* H3p = sm;
    u64* P1  = sm + 2052;
    u64* SX  = sm + 2052;
    u64* W1s = sm + 2310;
    u64* B1s = sm + 2374;
    float* W3f = (float*)(sm + 3140);
    float* W4f = (float*)(sm + 4420);
    u64* B2s = sm + 6980;
    u64* B3s = sm + 6996;
    u64* B4s = sm + 7028;

    {
        int c = tid >> 7, t = tid & 127;
        const float* xp = x + pair * 512 + c * 128 + t;
        SX[c * 128 + t] = pack2(xp[0], xp[256]);
    }
    for (int i = tid; i < 640;  i += 256) ((float4*)W3f)[i] = ((const float4*)g_qw3)[i];
    for (int i = tid; i < 1280; i += 256) ((float4*)W4f)[i] = ((const float4*)g_qw4)[i];
    if (tid < 64) W1s[tid] = dup2(g_qw1[tid]);
    else if (tid >= 64 && tid < 80)   B1s[tid - 64] = dup2(b1[tid - 64]);
    else if (tid >= 96 && tid < 112)  B2s[tid - 96] = dup2(b2[tid - 96]);
    else if (tid >= 128 && tid < 160) B3s[tid - 128] = dup2(b3[tid - 128]);
    else if (tid >= 160 && tid < 192) B4s[tid - 160] = dup2(b4[tid - 160]);
    __syncthreads();

    // L1
    if (tid < 254) {
        int cg = tid & 1, t = tid >> 1;
        u64 a00 = SX[t], a01 = SX[t + 1], a10 = SX[128 + t], a11 = SX[128 + t + 1];
        u64* o = H1 + t;
#pragma unroll
        for (int u = 0; u < 8; u++) {
            int co = cg * 8 + u;
            ulonglong2 w01 = lds2(W1s + co * 4);
            ulonglong2 w23 = lds2(W1s + co * 4 + 2);
            u64 acc = B1s[co];
            acc = ffma2(a00, w01.x, acc);
            acc = ffma2(a01, w01.y, acc);
            acc = ffma2(a10, w23.x, acc);
            acc = ffma2(a11, w23.y, acc);
            o[co * 128] = lrelu2(acc);
        }
    }
    __syncthreads();

    // L2
    {
        int co = lane & 15, half = lane >> 4;
        int t0 = 16 * wrp + 8 * half;
        u64 acc[8];
        u64 bb = B2s[co];
#pragma unroll
        for (int p = 0; p < 8; p++) acc[p] = bb;
        for (int ci = 0; ci < 16; ci++) {
            const u64* h = H1 + ci * 128 + t0;
            u64 a[10];
#pragma unroll
            for (int s = 0; s < 5; s++) {
                ulonglong2 v = lds2(h + 2 * s);
                a[2 * s] = v.x; a[2 * s + 1] = v.y;
            }
            u64 w0 = dup2(__ldg(g_qw2 + (ci * 3 + 0) * 16 + co));
            u64 w1 = dup2(__ldg(g_qw2 + (ci * 3 + 1) * 16 + co));
            u64 w2 = dup2(__ldg(g_qw2 + (ci * 3 + 2) * 16 + co));
#pragma unroll
            for (int p = 0; p < 8; p++) {
                u64 s = acc[p];
                s = ffma2(a[p],     w0, s);
                s = ffma2(a[p + 1], w1, s);
                s = ffma2(a[p + 2], w2, s);
                acc[p] = s;
            }
        }
        u64* o = P1 + co * 68;
#pragma unroll
        for (int i = 0; i < 4; i++) {
            int pq = 8 * wrp + 4 * half + i;
            if (pq < 62)
                o[pq] = lrelu2(max2(acc[2 * i], acc[2 * i + 1]));
        }
    }
    __syncthreads();

    // L3
    {
        int t0 = 8 * wrp;
        u64 acc[8];
        u64 bb = B3s[lane];
#pragma unroll
        for (int p = 0; p < 8; p++) acc[p] = bb;
        for (int ci = 0; ci < 16; ci++) {
            const u64* pb = P1 + ci * 68 + t0;
            u64 a[12];
#pragma unroll
            for (int j = 0; j < 6; j++) {
                ulonglong2 v = lds2(pb + 2 * j);
                a[2 * j] = v.x; a[2 * j + 1] = v.y;
            }
            const float* wf = W3f + ci * 160 + lane;
            u64 w0 = dup2(wf[0]),  u64w1 = dup2(wf[32]);
            u64 w2 = dup2(wf[64]), w3 = dup2(wf[96]), w4 = dup2(wf[128]);
#pragma unroll
            for (int p = 0; p < 8; p++) {
                u64 s = acc[p];
                s = ffma2(a[p],     w0, s);
                s = ffma2(a[p + 1], u64w1, s);
                s = ffma2(a[p + 2], w2, s);
                s = ffma2(a[p + 3], w3, s);
                s = ffma2(a[p + 4], w4, s);
                acc[p] = s;
            }
        }
        u64* ob = H3p + lane * 2;
#pragma unroll
        for (int i = 0; i < 4; i++) {
            int tp = 4 * wrp + i;
            if (tp < 29) {
                ulonglong2 v;
                v.x = lrelu2(acc[2 * i]);
                v.y = lrelu2(acc[2 * i + 1]);
                *reinterpret_cast<ulonglong2*>(ob + tp * 66) = v;
            }
        }
    }
    __syncthreads();

    // L4 -> global P2
    if (wrp < 7) {
        int tp0 = 4 * wrp;
        u64 acc[8];
        u64 bb = B4s[lane];
#pragma unroll
        for (int p = 0; p < 8; p++) acc[p] = bb;
        for (int ci = 0; ci < 32; ci++) {
            const u64* pb = H3p + tp0 * 66 + ci * 2;
            u64 a[12];
#pragma unroll
            for (int j = 0; j < 6; j++) {
                ulonglong2 v = lds2(pb + j * 66);
                a[2 * j] = v.x; a[2 * j + 1] = v.y;
            }
            const float* wf = W4f + ci * 160 + lane;
            u64 w0 = dup2(wf[0]),  w1 = dup2(wf[32]), w2 = dup2(wf[64]);
            u64 w3 = dup2(wf[96]), w4 = dup2(wf[128]);
#pragma unroll
            for (int p = 0; p < 8; p++) {
                u64 s = acc[p];
                s = ffma2(a[p],     w0, s);
                s = ffma2(a[p + 1], w1, s);
                s = ffma2(a[p + 2], w2, s);
                s = ffma2(a[p + 3], w3, s);
                s = ffma2(a[p + 4], w4, s);
                acc[p] = s;
            }
        }
        u64* ob = g_P2 + pair * 864 + lane;
#pragma unroll
        for (int i = 0; i < 4; i++) {
            int pq = 4 * wrp + i;
            if (pq < 27)
                ob[pq * 32] = lrelu2(max2(acc[2 * i], acc[2 * i + 1]));
        }
    }
}

// ---- dense kernel: 864->64->1 for 8 pairs (16 samples) ---------------------
// smem (u64): SP2 [0,6912) [q*864+j]; PART [6912,11008); HH [11008,11520)
#define DENSE_SMEM_U64 11520
#define DENSE_SMEM_BYTES (DENSE_SMEM_U64 * 8)

__global__ void __launch_bounds__(256, 2)
dense_kernel(const float* __restrict__ bd, const float* __restrict__ bo,
             float* __restrict__ out) {
    extern __shared__ u64 sm[];
    const int tid  = threadIdx.x;
    const int wrp  = tid >> 5;
    const int lane = tid & 31;
    const int blk  = blockIdx.x;

    u64* SP2  = sm;
    u64* PART = sm + 6912;
    u64* HH   = sm + 11008;

    // stage 8 pairs of P2 rows
    for (int i = tid; i < 3456; i += 256) {
        int q = i / 432, r = i - q * 432;
        ulonglong2 v = *((const ulonglong2*)(g_P2 + (blk * 8 + q) * 864) + r);
        *reinterpret_cast<ulonglong2*>(SP2 + q * 864 + 2 * r) = v;
    }
    __syncthreads();

    // 8 warps x 108-j chunks; lane covers (oc, oc+32) for 8 pairs
    {
        int j0 = wrp * 108;
        const float2* wdp = (const float2*)g_qwd;   // [idx][oc] = (w_oc, w_oc+32)
        u64 acc[16];
#pragma unroll
        for (int q = 0; q < 16; q++) acc[q] = 0ull;
#pragma unroll 2
        for (int g = 0; g < 54; g++) {
            int j = j0 + 2 * g;
            float2 wa = __ldg(wdp + j * 32 + lane);
            float2 wb = __ldg(wdp + (j + 1) * 32 + lane);
            u64 w0a = dup2(wa.x), w0b = dup2(wa.y);
            u64 w1a = dup2(wb.x), w1b = dup2(wb.y);
#pragma unroll
            for (int q = 0; q < 8; q++) {
                ulonglong2 a = lds2(SP2 + q * 864 + j);
                acc[q*2]   = ffma2(a.x, w0a, acc[q*2]);
                acc[q*2]   = ffma2(a.y, w1a, acc[q*2]);
                acc[q*2+1] = ffma2(a.x, w0b, acc[q*2+1]);
                acc[q*2+1] = ffma2(a.y, w1b, acc[q*2+1]);
            }
        }
        u64* pb = PART + wrp * 512;
#pragma unroll
        for (int q = 0; q < 8; q++) {
            pb[lane * 8 + q]        = acc[q*2];
            pb[(lane + 32) * 8 + q] = acc[q*2+1];
        }
    }
    __syncthreads();

    // reduce 8 chunks + bias + lrelu (512 items over 256 threads)
    for (int item = tid; item < 512; item += 256) {
        int oc = item >> 3, q = item & 7;
        u64 s = PART[oc * 8 + q];
#pragma unroll
        for (int c = 1; c < 8; c++) s = add2(s, PART[c * 512 + oc * 8 + q]);
        s = add2(s, dup2(bd[oc]));
        HH[q * 64 + oc] = lrelu2(s);
    }
    __syncthreads();

    // output 64 -> 1, one warp per pair q = 0..7
    {
        int q = wrp;
        float2 h0  = unpack2(HH[q * 64 + lane]);
        float2 h1v = unpack2(HH[q * 64 + 32 + lane]);
        float wl = g_qwo[lane], wh = g_qwo[lane + 32];
        float ax = h0.x * wl + h1v.x * wh;
        float ay = h0.y * wl + h1v.y * wh;
#pragma unroll
        for (int o = 16; o > 0; o >>= 1) {
            ax += __shfl_xor_sync(0xffffffffu, ax, o);
            ay += __shfl_xor_sync(0xffffffffu, ay, o);
        }
        if (lane == 0) {
            float bov = bo[0];
            reinterpret_cast<float2*>(out)[blk * 8 + q] =
                make_float2(ax + bov, ay + bov);
        }
    }
}

// ---- launcher --------------------------------------------------------------
extern "C" void kernel_launch(void* const* d_in, const int* in_sizes, int n_in,
                              void* d_out, int out_size) {
    const float* x  = (const float*)d_in[0];
    const float* w1 = (const float*)d_in[1];
    const float* b1 = (const float*)d_in[2];
    const float* w2 = (const float*)d_in[3];
    const float* b2 = (const float*)d_in[4];
    const float* w3 = (const float*)d_in[5];
    const float* b3 = (const float*)d_in[6];
    const float* w4 = (const float*)d_in[7];
    const float* b4 = (const float*)d_in[8];
    const float* wd = (const float*)d_in[9];
    const float* bd = (const float*)d_in[10];
    const float* wo = (const float*)d_in[11];
    const float* bo = (const float*)d_in[12];

    cudaFuncSetAttribute(conv_kernel,
                         cudaFuncAttributeMaxDynamicSharedMemorySize, CONV_SMEM_BYTES);
    cudaFuncSetAttribute(dense_kernel,
                         cudaFuncAttributeMaxDynamicSharedMemorySize, DENSE_SMEM_BYTES);

    scale_kernel<<<6, 256>>>(w1, w2, w3, w4, wd, wo);
    quantize_kernel<<<251, 256>>>(w1, w2, w3, w4, wd, wo);
    conv_kernel<<<16384, 256, CONV_SMEM_BYTES>>>(x, b1, b2, b3, b4);
    dense_kernel<<<2048, 256, DENSE_SMEM_BYTES>>>(bd, bo, (float*)d_out);
}

// round 10
// speedup vs baseline: 2.6122x; 1.0400x over previous
#include <cuda_runtime.h>
#include <cuda_bf16.h>

// ----------------------------------------------------------------------------
// QCNN, round 10: dense reverted to 4 pairs/block (46KB smem -> 3-4 CTAs/SM,
// occupancy was the dense binder, not weight traffic). Conv unchanged.
// ----------------------------------------------------------------------------

typedef unsigned long long u64;

__device__ __align__(16) float g_qw1[64];      // [co*4 + ci*2 + k]
__device__ __align__(16) float g_qw2[768];     // [(ci*3+k)*16 + co]
__device__ __align__(16) float g_qw3[2560];    // [(ci*5+k)*32 + co]
__device__ __align__(16) float g_qw4[5120];    // [(ci*5+k)*32 + co]
__device__ __align__(16) float g_qwd[55296];   // [idx=pq*32+co][oc*2+h]  h: +32
__device__ __align__(16) float g_qwo[64];
__device__ float g_scale[6];
__device__ __align__(16) u64   g_P2[16384 * 864];  // [pair][pq*32+co] f32x2

// ---- f32x2 helpers ---------------------------------------------------------
__device__ __forceinline__ u64 ffma2(u64 a, u64 b, u64 c) {
    u64 d;
    asm("fma.rn.f32x2 %0, %1, %2, %3;" : "=l"(d) : "l"(a), "l"(b), "l"(c));
    return d;
}
__device__ __forceinline__ u64 add2(u64 a, u64 b) {
    u64 d;
    asm("add.rn.f32x2 %0, %1, %2;" : "=l"(d) : "l"(a), "l"(b));
    return d;
}
__device__ __forceinline__ u64 pack2(float x, float y) {
    u64 d;
    asm("mov.b64 %0, {%1, %2};" : "=l"(d) : "f"(x), "f"(y));
    return d;
}
__device__ __forceinline__ float2 unpack2(u64 v) {
    float2 f;
    asm("mov.b64 {%0, %1}, %2;" : "=f"(f.x), "=f"(f.y) : "l"(v));
    return f;
}
__device__ __forceinline__ u64 dup2(float w) { return pack2(w, w); }
__device__ __forceinline__ u64 lrelu2(u64 v) {
    float2 f = unpack2(v);
    f.x = f.x > 0.0f ? f.x : 0.1f * f.x;
    f.y = f.y > 0.0f ? f.y : 0.1f * f.y;
    return pack2(f.x, f.y);
}
__device__ __forceinline__ u64 max2(u64 a, u64 b) {
    float2 fa = unpack2(a), fb = unpack2(b);
    return pack2(fmaxf(fa.x, fb.x), fmaxf(fa.y, fb.y));
}
__device__ __forceinline__ ulonglong2 lds2(const u64* p) {
    return *reinterpret_cast<const ulonglong2*>(p);
}

// ---- prep phase A: per-tensor scale (max|w| / 127) -------------------------
__global__ void scale_kernel(const float* __restrict__ w1,
                             const float* __restrict__ w2,
                             const float* __restrict__ w3,
                             const float* __restrict__ w4,
                             const float* __restrict__ wd,
                             const float* __restrict__ wo) {
    __shared__ float red[256];
    int b = blockIdx.x, tid = threadIdx.x;
    const float* src; int n;
    if (b == 0)      { src = w1; n = 64; }
    else if (b == 1) { src = w2; n = 768; }
    else if (b == 2) { src = w3; n = 2560; }
    else if (b == 3) { src = w4; n = 5120; }
    else if (b == 4) { src = wd; n = 55296; }
    else             { src = wo; n = 64; }
    float m = 0.0f;
    for (int i = tid; i < n; i += 256) m = fmaxf(m, fabsf(src[i]));
    red[tid] = m;
    __syncthreads();
    for (int s = 128; s > 0; s >>= 1) {
        if (tid < s) red[tid] = fmaxf(red[tid], red[tid + s]);
        __syncthreads();
    }
    if (tid == 0) g_scale[b] = red[0] / 127.0f;
}

// ---- prep phase B: quantize + permute, fully parallel ----------------------
__global__ void quantize_kernel(const float* __restrict__ w1,
                                const float* __restrict__ w2,
                                const float* __restrict__ w3,
                                const float* __restrict__ w4,
                                const float* __restrict__ wd,
                                const float* __restrict__ wo) {
    int blk = blockIdx.x, tid = threadIdx.x;
    int b, i;
    const float* src; float* dst; int n;
    if (blk < 1)        { b = 0; src = w1; dst = g_qw1; n = 64;    i = blk * 256 + tid; }
    else if (blk < 4)   { b = 1; src = w2; dst = g_qw2; n = 768;   i = (blk - 1) * 256 + tid; }
    else if (blk < 14)  { b = 2; src = w3; dst = g_qw3; n = 2560;  i = (blk - 4) * 256 + tid; }
    else if (blk < 34)  { b = 3; src = w4; dst = g_qw4; n = 5120;  i = (blk - 14) * 256 + tid; }
    else if (blk < 250) { b = 4; src = wd; dst = g_qwd; n = 55296; i = (blk - 34) * 256 + tid; }
    else                { b = 5; src = wo; dst = g_qwo; n = 64;    i = (blk - 250) * 256 + tid; }
    if (i >= n) return;
    float scale = g_scale[b];
    float q = rintf(src[i] / scale);               // round half-even == jnp.round
    q = fminf(fmaxf(q, -127.0f), 127.0f) * scale;
    int di = i;
    if (b == 1) {
        int co = i / 48, r = i - co * 48, ci = r / 3, k = r - ci * 3;
        di = (ci * 3 + k) * 16 + co;
    } else if (b == 2) {
        int co = i / 80, r = i - co * 80, ci = r / 5, k = r - ci * 5;
        di = (ci * 5 + k) * 32 + co;
    } else if (b == 3) {
        int co = i / 160, r = i - co * 160, ci = r / 5, k = r - ci * 5;
        di = (ci * 5 + k) * 32 + co;
    } else if (b == 4) {
        int o = i / 864, j = i - o * 864;
        int co = j / 27, pq = j - co * 27;
        int idx = pq * 32 + co;
        int oc = o & 31, h = o >> 5;
        di = idx * 64 + oc * 2 + h;
    }
    dst[di] = q;
}

// ---- conv kernel: L1..L4 for one sample-pair -------------------------------
#define CONV_SMEM_U64 7060
#define CONV_SMEM_BYTES (CONV_SMEM_U64 * 8)

__global__ void __launch_bounds__(256, 4)
conv_kernel(const float* __restrict__ x,
            const float* __restrict__ b1, const float* __restrict__ b2,
            const float* __restrict__ b3, const float* __restrict__ b4) {
    extern __shared__ u64 sm[];
    const int tid  = threadIdx.x;
    const int wrp  = tid >> 5;
    const int lane = tid & 31;
    const int pair = blockIdx.x;

    u64* H1  = sm;
    u64* H3p = sm;
    u64* P1  = sm + 2052;
    u64* SX  = sm + 2052;
    u64* W1s = sm + 2310;
    u64* B1s = sm + 2374;
    float* W3f = (float*)(sm + 3140);
    float* W4f = (float*)(sm + 4420);
    u64* B2s = sm + 6980;
    u64* B3s = sm + 6996;
    u64* B4s = sm + 7028;

    {
        int c = tid >> 7, t = tid & 127;
        const float* xp = x + pair * 512 + c * 128 + t;
        SX[c * 128 + t] = pack2(xp[0], xp[256]);
    }
    for (int i = tid; i < 640;  i += 256) ((float4*)W3f)[i] = ((const float4*)g_qw3)[i];
    for (int i = tid; i < 1280; i += 256) ((float4*)W4f)[i] = ((const float4*)g_qw4)[i];
    if (tid < 64) W1s[tid] = dup2(g_qw1[tid]);
    else if (tid >= 64 && tid < 80)   B1s[tid - 64] = dup2(b1[tid - 64]);
    else if (tid >= 96 && tid < 112)  B2s[tid - 96] = dup2(b2[tid - 96]);
    else if (tid >= 128 && tid < 160) B3s[tid - 128] = dup2(b3[tid - 128]);
    else if (tid >= 160 && tid < 192) B4s[tid - 160] = dup2(b4[tid - 160]);
    __syncthreads();

    // L1
    if (tid < 254) {
        int cg = tid & 1, t = tid >> 1;
        u64 a00 = SX[t], a01 = SX[t + 1], a10 = SX[128 + t], a11 = SX[128 + t + 1];
        u64* o = H1 + t;
#pragma unroll
        for (int u = 0; u < 8; u++) {
            int co = cg * 8 + u;
            ulonglong2 w01 = lds2(W1s + co * 4);
            ulonglong2 w23 = lds2(W1s + co * 4 + 2);
            u64 acc = B1s[co];
            acc = ffma2(a00, w01.x, acc);
            acc = ffma2(a01, w01.y, acc);
            acc = ffma2(a10, w23.x, acc);
            acc = ffma2(a11, w23.y, acc);
            o[co * 128] = lrelu2(acc);
        }
    }
    __syncthreads();

    // L2
    {
        int co = lane & 15, half = lane >> 4;
        int t0 = 16 * wrp + 8 * half;
        u64 acc[8];
        u64 bb = B2s[co];
#pragma unroll
        for (int p = 0; p < 8; p++) acc[p] = bb;
        for (int ci = 0; ci < 16; ci++) {
            const u64* h = H1 + ci * 128 + t0;
            u64 a[10];
#pragma unroll
            for (int s = 0; s < 5; s++) {
                ulonglong2 v = lds2(h + 2 * s);
                a[2 * s] = v.x; a[2 * s + 1] = v.y;
            }
            u64 w0 = dup2(__ldg(g_qw2 + (ci * 3 + 0) * 16 + co));
            u64 w1 = dup2(__ldg(g_qw2 + (ci * 3 + 1) * 16 + co));
            u64 w2 = dup2(__ldg(g_qw2 + (ci * 3 + 2) * 16 + co));
#pragma unroll
            for (int p = 0; p < 8; p++) {
                u64 s = acc[p];
                s = ffma2(a[p],     w0, s);
                s = ffma2(a[p + 1], w1, s);
                s = ffma2(a[p + 2], w2, s);
                acc[p] = s;
            }
        }
        u64* o = P1 + co * 68;
#pragma unroll
        for (int i = 0; i < 4; i++) {
            int pq = 8 * wrp + 4 * half + i;
            if (pq < 62)
                o[pq] = lrelu2(max2(acc[2 * i], acc[2 * i + 1]));
        }
    }
    __syncthreads();

    // L3
    {
        int t0 = 8 * wrp;
        u64 acc[8];
        u64 bb = B3s[lane];
#pragma unroll
        for (int p = 0; p < 8; p++) acc[p] = bb;
        for (int ci = 0; ci < 16; ci++) {
            const u64* pb = P1 + ci * 68 + t0;
            u64 a[12];
#pragma unroll
            for (int j = 0; j < 6; j++) {
                ulonglong2 v = lds2(pb + 2 * j);
                a[2 * j] = v.x; a[2 * j + 1] = v.y;
            }
            const float* wf = W3f + ci * 160 + lane;
            u64 w0 = dup2(wf[0]),  w1 = dup2(wf[32]), w2 = dup2(wf[64]);
            u64 w3 = dup2(wf[96]), w4 = dup2(wf[128]);
#pragma unroll
            for (int p = 0; p < 8; p++) {
                u64 s = acc[p];
                s = ffma2(a[p],     w0, s);
                s = ffma2(a[p + 1], w1, s);
                s = ffma2(a[p + 2], w2, s);
                s = ffma2(a[p + 3], w3, s);
                s = ffma2(a[p + 4], w4, s);
                acc[p] = s;
            }
        }
        u64* ob = H3p + lane * 2;
#pragma unroll
        for (int i = 0; i < 4; i++) {
            int tp = 4 * wrp + i;
            if (tp < 29) {
                ulonglong2 v;
                v.x = lrelu2(acc[2 * i]);
                v.y = lrelu2(acc[2 * i + 1]);
                *reinterpret_cast<ulonglong2*>(ob + tp * 66) = v;
            }
        }
    }
    __syncthreads();

    // L4 -> global P2
    if (wrp < 7) {
        int tp0 = 4 * wrp;
        u64 acc[8];
        u64 bb = B4s[lane];
#pragma unroll
        for (int p = 0; p < 8; p++) acc[p] = bb;
        for (int ci = 0; ci < 32; ci++) {
            const u64* pb = H3p + tp0 * 66 + ci * 2;
            u64 a[12];
#pragma unroll
            for (int j = 0; j < 6; j++) {
                ulonglong2 v = lds2(pb + j * 66);
                a[2 * j] = v.x; a[2 * j + 1] = v.y;
            }
            const float* wf = W4f + ci * 160 + lane;
            u64 w0 = dup2(wf[0]),  w1 = dup2(wf[32]), w2 = dup2(wf[64]);
            u64 w3 = dup2(wf[96]), w4 = dup2(wf[128]);
#pragma unroll
            for (int p = 0; p < 8; p++) {
                u64 s = acc[p];
                s = ffma2(a[p],     w0, s);
                s = ffma2(a[p + 1], w1, s);
                s = ffma2(a[p + 2], w2, s);
                s = ffma2(a[p + 3], w3, s);
                s = ffma2(a[p + 4], w4, s);
                acc[p] = s;
            }
        }
        u64* ob = g_P2 + pair * 864 + lane;
#pragma unroll
        for (int i = 0; i < 4; i++) {
            int pq = 4 * wrp + i;
            if (pq < 27)
                ob[pq * 32] = lrelu2(max2(acc[2 * i], acc[2 * i + 1]));
        }
    }
}

// ---- dense kernel: 864->64->1 for 4 pairs (8 samples) ----------------------
// smem (u64): SP2 [0,3456) [q*864+j]; PART [3456,5504); HH [5504,5760)
#define DENSE_SMEM_U64 5760
#define DENSE_SMEM_BYTES (DENSE_SMEM_U64 * 8)

__global__ void __launch_bounds__(256, 3)
dense_kernel(const float* __restrict__ bd, const float* __restrict__ bo,
             float* __restrict__ out) {
    extern __shared__ u64 sm[];
    const int tid  = threadIdx.x;
    const int wrp  = tid >> 5;
    const int lane = tid & 31;
    const int blk  = blockIdx.x;

    u64* SP2  = sm;
    u64* PART = sm + 3456;
    u64* HH   = sm + 5504;

    // stage 4 pairs of P2 rows
#pragma unroll 2
    for (int i = tid; i < 1728; i += 256) {
        int q = i / 432, r = i - q * 432;
        ulonglong2 v = __ldg((const ulonglong2*)(g_P2 + (blk * 4 + q) * 864) + r);
        *reinterpret_cast<ulonglong2*>(SP2 + q * 864 + 2 * r) = v;
    }
    __syncthreads();

    // 8 warps x 108-j chunks; lane covers (oc, oc+32) for 4 pairs
    {
        int j0 = wrp * 108;
        const float2* wdp = (const float2*)g_qwd;   // [idx][oc] = (w_oc, w_oc+32)
        u64 acc[8] = {0, 0, 0, 0, 0, 0, 0, 0};      // [q*2 + h]
#pragma unroll 4
        for (int g = 0; g < 54; g++) {
            int j = j0 + 2 * g;
            float2 wa = __ldg(wdp + j * 32 + lane);
            float2 wb = __ldg(wdp + (j + 1) * 32 + lane);
            u64 w0a = dup2(wa.x), w0b = dup2(wa.y);
            u64 w1a = dup2(wb.x), w1b = dup2(wb.y);
#pragma unroll
            for (int q = 0; q < 4; q++) {
                ulonglong2 a = lds2(SP2 + q * 864 + j);
                acc[q*2]   = ffma2(a.x, w0a, acc[q*2]);
                acc[q*2]   = ffma2(a.y, w1a, acc[q*2]);
                acc[q*2+1] = ffma2(a.x, w0b, acc[q*2+1]);
                acc[q*2+1] = ffma2(a.y, w1b, acc[q*2+1]);
            }
        }
        u64* pb = PART + wrp * 256;
#pragma unroll
        for (int q = 0; q < 4; q++) {
            pb[lane * 4 + q]        = acc[q*2];
            pb[(lane + 32) * 4 + q] = acc[q*2+1];
        }
    }
    __syncthreads();

    // reduce 8 chunks + bias + lrelu
    {
        int oc = tid & 63, q = tid >> 6;
        u64 s = PART[oc * 4 + q];
#pragma unroll
        for (int c = 1; c < 8; c++) s = add2(s, PART[c * 256 + oc * 4 + q]);
        s = add2(s, dup2(bd[oc]));
        HH[q * 64 + oc] = lrelu2(s);
    }
    __syncthreads();

    // output 64 -> 1
    if (tid < 128) {
        int q = tid >> 5, ln = tid & 31;
        float2 h0  = unpack2(HH[q * 64 + ln]);
        float2 h1v = unpack2(HH[q * 64 + 32 + ln]);
        float wl = g_qwo[ln], wh = g_qwo[ln + 32];
        float ax = h0.x * wl + h1v.x * wh;
        float ay = h0.y * wl + h1v.y * wh;
#pragma unroll
        for (int o = 16; o > 0; o >>= 1) {
            ax += __shfl_xor_sync(0xffffffffu, ax, o);
            ay += __shfl_xor_sync(0xffffffffu, ay, o);
        }
        if (ln == 0) {
            float bov = bo[0];
            reinterpret_cast<float2*>(out)[blk * 4 + q] =
                make_float2(ax + bov, ay + bov);
        }
    }
}

// ---- launcher --------------------------------------------------------------
extern "C" void kernel_launch(void* const* d_in, const int* in_sizes, int n_in,
                              void* d_out, int out_size) {
    const float* x  = (const float*)d_in[0];
    const float* w1 = (const float*)d_in[1];
    const float* b1 = (const float*)d_in[2];
    const float* w2 = (const float*)d_in[3];
    const float* b2 = (const float*)d_in[4];
    const float* w3 = (const float*)d_in[5];
    const float* b3 = (const float*)d_in[6];
    const float* w4 = (const float*)d_in[7];
    const float* b4 = (const float*)d_in[8];
    const float* wd = (const float*)d_in[9];
    const float* bd = (const float*)d_in[10];
    const float* wo = (const float*)d_in[11];
    const float* bo = (const float*)d_in[12];

    cudaFuncSetAttribute(conv_kernel,
                         cudaFuncAttributeMaxDynamicSharedMemorySize, CONV_SMEM_BYTES);
    cudaFuncSetAttribute(dense_kernel,
                         cudaFuncAttributeMaxDynamicSharedMemorySize, DENSE_SMEM_BYTES);

    scale_kernel<<<6, 256>>>(w1, w2, w3, w4, wd, wo);
    quantize_kernel<<<251, 256>>>(w1, w2, w3, w4, wd, wo);
    conv_kernel<<<16384, 256, CONV_SMEM_BYTES>>>(x, b1, b2, b3, b4);
    dense_kernel<<<4096, 256, DENSE_SMEM_BYTES>>>(bd, bo, (float*)d_out);
}